// round 1
// baseline (speedup 1.0000x reference)
#include <cuda_runtime.h>
#include <math.h>

// ---------------- problem constants ----------------
#define TS     8
#define BATCH  16
#define NPG    4096
#define NEDGE  (TS*BATCH*32768)   // 4,194,304 edges total (all timesteps)
#define NG     (TS*BATCH)         // 128 graphs
#define EPSN   1e-5f

// ---------------- static device scratch ----------------
__device__ float g_XW [67108864];   // 268 MB : x @ W        (max 524288 x 128)
__device__ float g_AGG[67108864];   // 268 MB : agg / y / normalized x
__device__ float g_X  [33554432];   // 134 MB : compacted layer input (max 262144 x 128)
__device__ float g_DEG [524288];
__device__ float g_DINV[524288];
__device__ float g_SCORE[524288];
__device__ int   g_MAP  [524288];
__device__ int   g_PERMG[262144];
__device__ float g_GATE [262144];
__device__ int   g_SRC[NEDGE];
__device__ int   g_DST[NEDGE];
__device__ float g_M  [NEDGE];
__device__ float g_SUMS[NG*256];    // becomes MU
__device__ float g_VARS[NG*256];    // becomes rsigma
__device__ float g_PMEAN[NG*256];
__device__ float g_PMAX [NG*256];

// ---------------- utility kernels ----------------
__global__ void k_zero(float* p, size_t cnt){
    size_t i = (size_t)blockIdx.x*blockDim.x + threadIdx.x;
    size_t stride = (size_t)gridDim.x*blockDim.x;
    for (; i < cnt; i += stride) p[i] = 0.f;
}

__global__ void k_edge_init(const int* __restrict__ ei){
    int idx = blockIdx.x*blockDim.x + threadIdx.x;
    if (idx >= NEDGE) return;
    const int E = 32768*BATCH;         // 524288 edges per timestep
    int t = idx / E, e = idx % E;
    int base = t * (BATCH*NPG);
    g_SRC[idx] = ei[(size_t)t*2*E + e]     + base;
    g_DST[idx] = ei[(size_t)t*2*E + E + e] + base;
    g_M[idx]   = 1.f;
}

__global__ void k_deg_init(int ntot){
    int i = blockIdx.x*blockDim.x + threadIdx.x;
    if (i < ntot) g_DEG[i] = 1.f;
}

__global__ void k_deg_scatter(){
    int e = blockIdx.x*blockDim.x + threadIdx.x;
    if (e >= NEDGE) return;
    float m = g_M[e];
    if (m != 0.f) atomicAdd(&g_DEG[g_DST[e]], m);
}

__global__ void k_dinv(int ntot){
    int i = blockIdx.x*blockDim.x + threadIdx.x;
    if (i < ntot) g_DINV[i] = rsqrtf(g_DEG[i]);
}

// ---------------- SGEMM: C[M,N] = A[M,K] * W[K,N], row-major ----------------
__global__ void k_sgemm(const float* __restrict__ A, const float* __restrict__ Bw,
                        float* __restrict__ C, int M, int N, int K){
    __shared__ float As[16][64];
    __shared__ float Bs[16][64];
    int tid = threadIdx.x;
    int tx = tid & 15, ty = tid >> 4;
    int bm = blockIdx.y * 64, bn = blockIdx.x * 64;
    float acc[4][4] = {};
    for (int k0 = 0; k0 < K; k0 += 16){
        #pragma unroll
        for (int i = 0; i < 4; i++){
            int e = i*256 + tid;
            int m = e >> 4, kk = e & 15;
            As[kk][m] = (k0 + kk < K) ? A[(size_t)(bm + m)*K + k0 + kk] : 0.f;
            int kk2 = e >> 6, nn = e & 63;
            Bs[kk2][nn] = (k0 + kk2 < K) ? Bw[(size_t)(k0 + kk2)*N + bn + nn] : 0.f;
        }
        __syncthreads();
        #pragma unroll
        for (int kk = 0; kk < 16; kk++){
            float4 a = *(const float4*)&As[kk][ty*4];
            float4 b = *(const float4*)&Bs[kk][tx*4];
            float av[4] = {a.x,a.y,a.z,a.w};
            float bv[4] = {b.x,b.y,b.z,b.w};
            #pragma unroll
            for (int i = 0; i < 4; i++)
                #pragma unroll
                for (int j = 0; j < 4; j++)
                    acc[i][j] += av[i]*bv[j];
        }
        __syncthreads();
    }
    #pragma unroll
    for (int i = 0; i < 4; i++){
        size_t row = bm + ty*4 + i;
        float4 o = {acc[i][0], acc[i][1], acc[i][2], acc[i][3]};
        *(float4*)&C[row*N + bn + tx*4] = o;
    }
}

// ---------------- edge message scatter: warp per edge ----------------
__global__ void k_scatter(int f){
    int warp = (blockIdx.x*blockDim.x + threadIdx.x) >> 5;
    int lane = threadIdx.x & 31;
    if (warp >= NEDGE) return;
    float m = g_M[warp];
    if (m == 0.f) return;
    int s = g_SRC[warp], d = g_DST[warp];
    float coef = g_DINV[s]*g_DINV[d]*m;
    const float* xs = g_XW + (size_t)s*f;
    float*       ad = g_AGG + (size_t)d*f;
    for (int fc = lane*4; fc < f; fc += 128){
        float4 v = *(const float4*)&xs[fc];
        atomicAdd(&ad[fc+0], v.x*coef);
        atomicAdd(&ad[fc+1], v.y*coef);
        atomicAdd(&ad[fc+2], v.z*coef);
        atomicAdd(&ad[fc+3], v.w*coef);
    }
}

// ---------------- combine self-loop + bias ----------------
__global__ void k_combine(const float* __restrict__ bias, int ntot, int f){
    size_t idx = (size_t)blockIdx.x*blockDim.x + threadIdx.x;
    size_t cnt = (size_t)ntot*f;
    if (idx >= cnt) return;
    int node = (int)(idx / f);
    int fi   = (int)(idx % f);
    float di = g_DINV[node];
    g_AGG[idx] = g_AGG[idx] + g_XW[idx]*(di*di) + bias[fi];
}

// ---------------- GraphNorm two-pass ----------------
__global__ void k_norm_sum(int n, int f){
    int g = blockIdx.x, fi = threadIdx.x;
    int ch = (n + gridDim.y - 1)/gridDim.y;
    int s0 = blockIdx.y*ch, s1 = min(s0+ch, n);
    float s = 0.f;
    for (int i = s0; i < s1; i++) s += g_AGG[((size_t)g*n + i)*f + fi];
    atomicAdd(&g_SUMS[g*f + fi], s);
}
__global__ void k_mu(int n, int f){
    int i = blockIdx.x*blockDim.x + threadIdx.x;
    if (i < NG*f) g_SUMS[i] *= (1.f/(float)n);
}
__global__ void k_norm_var(const float* __restrict__ ga, int n, int f){
    int g = blockIdx.x, fi = threadIdx.x;
    int ch = (n + gridDim.y - 1)/gridDim.y;
    int s0 = blockIdx.y*ch, s1 = min(s0+ch, n);
    float amu = ga[fi]*g_SUMS[g*f + fi];
    float s = 0.f;
    for (int i = s0; i < s1; i++){
        float o = g_AGG[((size_t)g*n + i)*f + fi] - amu;
        s += o*o;
    }
    atomicAdd(&g_VARS[g*f + fi], s);
}
__global__ void k_rs(int n, int f){
    int i = blockIdx.x*blockDim.x + threadIdx.x;
    if (i < NG*f) g_VARS[i] = rsqrtf(g_VARS[i]*(1.f/(float)n) + EPSN);
}

// ---------------- normalize + relu + topk score ----------------
__global__ void k_norm_apply(const float* __restrict__ gw, const float* __restrict__ gb,
                             const float* __restrict__ ga, const float* __restrict__ pw,
                             int n, int f){
    int node = blockIdx.x, fi = threadIdx.x;
    int g = node / n;
    size_t off = (size_t)node*f + fi;
    float mu = g_SUMS[g*f + fi], rs = g_VARS[g*f + fi];
    float x = gw[fi]*(g_AGG[off] - ga[fi]*mu)*rs + gb[fi];
    x = fmaxf(x, 0.f);
    g_AGG[off] = x;
    __shared__ float sd[256], sw2[256];
    float p = pw[fi];
    sd[fi] = x*p; sw2[fi] = p*p;
    __syncthreads();
    for (int st = blockDim.x >> 1; st > 0; st >>= 1){
        if (fi < st){ sd[fi] += sd[fi+st]; sw2[fi] += sw2[fi+st]; }
        __syncthreads();
    }
    if (fi == 0) g_SCORE[node] = tanhf(sd[0]*rsqrtf(sw2[0]));
}

// ---------------- per-graph exact top-k (radix select + index-order compaction) ----
__global__ void k_topk(int n, int k){
    __shared__ unsigned keys[4096];
    __shared__ int hist[256];
    __shared__ unsigned sh_prefix;
    __shared__ int sh_rem;
    __shared__ int sg[512], se[512];
    __shared__ int base_g, base_e;

    int g = blockIdx.x;
    int tid = threadIdx.x;
    const float* sc = g_SCORE + (size_t)g*n;

    for (int i = tid; i < n; i += blockDim.x){
        unsigned u = __float_as_uint(sc[i]);
        u = (u & 0x80000000u) ? ~u : (u | 0x80000000u);
        keys[i] = u;
    }
    if (tid == 0){ sh_prefix = 0u; sh_rem = k; }
    __syncthreads();

    for (int shift = 24; shift >= 0; shift -= 8){
        for (int i = tid; i < 256; i += blockDim.x) hist[i] = 0;
        __syncthreads();
        unsigned pmask = (shift == 24) ? 0u : (0xFFFFFFFFu << (shift + 8));
        unsigned pref = sh_prefix;
        for (int i = tid; i < n; i += blockDim.x){
            unsigned u = keys[i];
            if ((u & pmask) == pref) atomicAdd(&hist[(u >> shift) & 0xFF], 1);
        }
        __syncthreads();
        if (tid == 0){
            int rem = sh_rem, b;
            for (b = 255; b >= 0; b--){
                if (rem <= hist[b]) break;
                rem -= hist[b];
            }
            sh_prefix |= ((unsigned)b) << shift;
            sh_rem = rem;
        }
        __syncthreads();
    }
    unsigned thr = sh_prefix;
    int need = sh_rem;              // # of keys == thr to keep
    if (tid == 0){ base_g = 0; base_e = 0; }
    __syncthreads();

    for (int c0 = 0; c0 < n; c0 += blockDim.x){
        int i = c0 + tid;
        int gf = 0, ef = 0;
        if (i < n){
            unsigned u = keys[i];
            gf = (u > thr);
            ef = (u == thr);
        }
        sg[tid] = gf; se[tid] = ef;
        __syncthreads();
        for (int st = 1; st < blockDim.x; st <<= 1){
            int vg = 0, ve = 0;
            if (tid >= st){ vg = sg[tid-st]; ve = se[tid-st]; }
            __syncthreads();
            sg[tid] += vg; se[tid] += ve;
            __syncthreads();
        }
        if (i < n){
            int g_before = base_g + sg[tid] - gf;
            int e_before = base_e + se[tid] - ef;
            bool kept = gf || (ef && (e_before < need));
            int oldg = g*n + i;
            if (kept){
                int newlocal = g_before + min(e_before, need);
                int newglobal = g*k + newlocal;
                g_MAP[oldg]      = newglobal;
                g_PERMG[newglobal] = oldg;
                g_GATE[newglobal]  = sc[i];
            } else {
                g_MAP[oldg] = -1;
            }
        }
        __syncthreads();
        if (tid == 0){ base_g += sg[blockDim.x-1]; base_e += se[blockDim.x-1]; }
        __syncthreads();
    }
}

// ---------------- gather compacted, gated nodes ----------------
__global__ void k_gather(int tot_new, int f){
    int per = f >> 2;
    size_t idx = (size_t)blockIdx.x*blockDim.x + threadIdx.x;
    if (idx >= (size_t)tot_new*per) return;
    int j  = (int)(idx / per);
    int fc = (int)(idx % per)*4;
    int old = g_PERMG[j];
    float gv = g_GATE[j];
    float4 v = *(const float4*)&g_AGG[(size_t)old*f + fc];
    float4 o = {v.x*gv, v.y*gv, v.z*gv, v.w*gv};
    *(float4*)&g_X[(size_t)j*f + fc] = o;
}

// ---------------- remap edges to new node ids ----------------
__global__ void k_remap(){
    int e = blockIdx.x*blockDim.x + threadIdx.x;
    if (e >= NEDGE) return;
    if (g_M[e] == 0.f) return;
    int s = g_MAP[g_SRC[e]], d = g_MAP[g_DST[e]];
    if (s >= 0 && d >= 0){ g_SRC[e] = s; g_DST[e] = d; }
    else { g_M[e] = 0.f; g_SRC[e] = 0; g_DST[e] = 0; }
}

// ---------------- readout: mean/max over 512 nodes, 256 feats ----------------
__global__ void k_readout(){
    int gg = blockIdx.x;          // graph (t*B + b)
    int f  = threadIdx.x;         // 256 threads
    const float* base = g_X + (size_t)gg*512*256;
    float s = 0.f, mx = -INFINITY;
    for (int i = 0; i < 512; i++){
        float v = base[(size_t)i*256 + f];
        s += v;
        mx = fmaxf(mx, v);
    }
    g_PMEAN[gg*256 + f] = s*(1.f/512.f);
    g_PMAX [gg*256 + f] = mx;
}

__global__ void k_final(float* __restrict__ out){
    int idx = blockIdx.x*blockDim.x + threadIdx.x;
    if (idx >= BATCH*512) return;
    int b = idx / 512, c = idx % 512;
    float acc = 0.f;
    if (c < 256){
        for (int t = 0; t < TS; t++) acc += g_PMEAN[(t*BATCH + b)*256 + c];
    } else {
        for (int t = 0; t < TS; t++) acc += g_PMAX[(t*BATCH + b)*256 + (c-256)];
    }
    out[idx] = acc*(1.f/(float)TS);
}

// ---------------- host orchestration ----------------
extern "C" void kernel_launch(void* const* d_in, const int* in_sizes, int n_in,
                              void* d_out, int out_size){
    const float* x_seq = (const float*)d_in[0];
    const int*   ei    = (const int*)  d_in[1];
    const float* W [3] = {(const float*)d_in[2],  (const float*)d_in[4],  (const float*)d_in[6]};
    const float* bb[3] = {(const float*)d_in[3],  (const float*)d_in[5],  (const float*)d_in[7]};
    const float* gw[3] = {(const float*)d_in[8],  (const float*)d_in[11], (const float*)d_in[14]};
    const float* gb[3] = {(const float*)d_in[9],  (const float*)d_in[12], (const float*)d_in[15]};
    const float* ga[3] = {(const float*)d_in[10], (const float*)d_in[13], (const float*)d_in[16]};
    const float* pw[3] = {(const float*)d_in[17], (const float*)d_in[18], (const float*)d_in[19]};
    float* out = (float*)d_out;

    float *pXW, *pAGG, *pX, *pSUMS, *pVARS;
    cudaGetSymbolAddress((void**)&pXW,   g_XW);
    cudaGetSymbolAddress((void**)&pAGG,  g_AGG);
    cudaGetSymbolAddress((void**)&pX,    g_X);
    cudaGetSymbolAddress((void**)&pSUMS, g_SUMS);
    cudaGetSymbolAddress((void**)&pVARS, g_VARS);

    k_edge_init<<<NEDGE/256, 256>>>(ei);

    const int nin [3] = {4096, 2048, 1024};
    const int nk  [3] = {2048, 1024, 512};
    const int fin [3] = {100, 128, 128};
    const int fout[3] = {128, 128, 256};

    const float* A = x_seq;
    for (int l = 0; l < 3; l++){
        int n = nin[l], k = nk[l], fi = fin[l], fo = fout[l];
        int ntot = NG * n;
        size_t cnt = (size_t)ntot * fo;

        k_zero<<<4096, 256>>>(pAGG, cnt);
        k_zero<<<32, 256>>>(pSUMS, (size_t)NG*fo);
        k_zero<<<32, 256>>>(pVARS, (size_t)NG*fo);
        k_deg_init<<<(ntot + 255)/256, 256>>>(ntot);

        dim3 gemm_grid(fo/64, ntot/64);
        k_sgemm<<<gemm_grid, 256>>>(A, W[l], pXW, ntot, fo, fi);

        k_deg_scatter<<<NEDGE/256, 256>>>();
        k_dinv<<<(ntot + 255)/256, 256>>>(ntot);
        k_scatter<<<NEDGE/8, 256>>>(fo);
        k_combine<<<(int)((cnt + 255)/256), 256>>>(bb[l], ntot, fo);

        k_norm_sum<<<dim3(NG, 16), fo>>>(n, fo);
        k_mu<<<(NG*fo + 255)/256, 256>>>(n, fo);
        k_norm_var<<<dim3(NG, 16), fo>>>(ga[l], n, fo);
        k_rs<<<(NG*fo + 255)/256, 256>>>(n, fo);
        k_norm_apply<<<ntot, fo>>>(gw[l], gb[l], ga[l], pw[l], n, fo);

        k_topk<<<NG, 512>>>(n, k);
        int tot_new = NG * k;
        k_gather<<<(int)(((size_t)tot_new*(fo/4) + 255)/256), 256>>>(tot_new, fo);
        k_remap<<<NEDGE/256, 256>>>();

        A = pX;
    }

    k_readout<<<NG, 256>>>();
    k_final<<<(BATCH*512 + 255)/256, 256>>>(out);
}

// round 2
// speedup vs baseline: 1.6659x; 1.6659x over previous
#include <cuda_runtime.h>
#include <math.h>

// ---------------- problem constants ----------------
#define TS     8
#define BATCH  16
#define NPG    4096
#define NEDGE  (TS*BATCH*32768)   // 4,194,304 edges (all timesteps, layer 1)
#define NG     (TS*BATCH)         // 128 graphs
#define EPSN   1e-5f
#define MAXN   524288

// ---------------- static device scratch ----------------
__device__ float g_XW [67108864];   // x @ W        (max 524288 x 128)
__device__ float g_AGG[67108864];   // gcn out / normalized x
__device__ float g_X  [33554432];   // compacted layer input
__device__ float g_DINV[MAXN];
__device__ float g_SCORE[MAXN];
__device__ int   g_MAP [MAXN];
__device__ int   g_PERMG[262144];
__device__ float g_GATE [262144];
__device__ int   g_CNT[MAXN];       // in-degree counts
__device__ int   g_CUR[MAXN];       // fill cursors
__device__ int   g_ROW[MAXN];       // CSR row starts (exclusive scan)
__device__ int   g_BSUM[1024];
__device__ int   g_CSRC[NEDGE];     // CSR: src node per slot
__device__ float g_CW [NEDGE];      // CSR: edge coefficient dinv[s]*dinv[d]
__device__ int   g_ESRC[2][NEDGE];  // double-buffered compacted edge lists
__device__ int   g_EDST[2][NEDGE];
__device__ int   g_ECNT[2];
__device__ float g_STATS[2*NG*256]; // [0]: sum->mu, [NG*256]: sumsq->rsigma
__device__ float g_PMEAN[NG*256];
__device__ float g_PMAX [NG*256];

// ---------------- utility ----------------
__global__ void k_zero(float* p, size_t cnt){
    size_t i = (size_t)blockIdx.x*blockDim.x + threadIdx.x;
    size_t stride = (size_t)gridDim.x*blockDim.x;
    for (; i < cnt; i += stride) p[i] = 0.f;
}
__global__ void k_zeroi(int* p, int cnt){
    int i = blockIdx.x*blockDim.x + threadIdx.x;
    if (i < cnt) p[i] = 0;
}

__global__ void k_edge_init(const int* __restrict__ ei){
    int idx = blockIdx.x*blockDim.x + threadIdx.x;
    if (idx == 0){ g_ECNT[0] = NEDGE; g_ECNT[1] = 0; }
    if (idx >= NEDGE) return;
    const int E = 32768*BATCH;         // 524288 edges per timestep
    int t = idx / E, e = idx % E;
    int base = t * (BATCH*NPG);
    g_ESRC[0][idx] = ei[(size_t)t*2*E + e]     + base;
    g_EDST[0][idx] = ei[(size_t)t*2*E + E + e] + base;
}

// ---------------- CSR build ----------------
__global__ void k_count(int cur){
    int e = blockIdx.x*blockDim.x + threadIdx.x;
    if (e >= g_ECNT[cur]) return;
    atomicAdd(&g_CNT[g_EDST[cur][e]], 1);
}

__global__ void k_scan1(int n){   // exclusive scan of g_CNT -> g_ROW, block sums -> g_BSUM
    __shared__ int sh[512];
    int i = blockIdx.x*512 + threadIdx.x;
    int v = (i < n) ? g_CNT[i] : 0;
    sh[threadIdx.x] = v;
    __syncthreads();
    for (int st = 1; st < 512; st <<= 1){
        int t = (threadIdx.x >= st) ? sh[threadIdx.x - st] : 0;
        __syncthreads();
        sh[threadIdx.x] += t;
        __syncthreads();
    }
    if (i < n) g_ROW[i] = sh[threadIdx.x] - v;
    if (threadIdx.x == 511) g_BSUM[blockIdx.x] = sh[511];
}
__global__ void k_scan2(int nb){  // exclusive scan of block sums (nb <= 1024)
    __shared__ int sh[1024];
    int v = (threadIdx.x < nb) ? g_BSUM[threadIdx.x] : 0;
    sh[threadIdx.x] = v;
    __syncthreads();
    for (int st = 1; st < 1024; st <<= 1){
        int t = (threadIdx.x >= st) ? sh[threadIdx.x - st] : 0;
        __syncthreads();
        sh[threadIdx.x] += t;
        __syncthreads();
    }
    if (threadIdx.x < nb) g_BSUM[threadIdx.x] = sh[threadIdx.x] - v;
}
__global__ void k_scan3(int n){
    int i = blockIdx.x*512 + threadIdx.x;
    if (i < n) g_ROW[i] += g_BSUM[blockIdx.x];
}

__global__ void k_dinv(int ntot){
    int i = blockIdx.x*blockDim.x + threadIdx.x;
    if (i < ntot) g_DINV[i] = rsqrtf(1.f + (float)g_CNT[i]);
}

__global__ void k_fill(int cur){
    int e = blockIdx.x*blockDim.x + threadIdx.x;
    if (e >= g_ECNT[cur]) return;
    int s = g_ESRC[cur][e], d = g_EDST[cur][e];
    int slot = g_ROW[d] + atomicAdd(&g_CUR[d], 1);
    g_CSRC[slot] = s;
    g_CW[slot]   = g_DINV[s]*g_DINV[d];
}

// ---------------- SGEMM 128x128x8, 8x8 per thread ----------------
__global__ void k_sgemm(const float* __restrict__ A, const float* __restrict__ Bw,
                        float* __restrict__ C, int M, int N, int K){
    __shared__ float As[8][128];
    __shared__ float Bs[8][128];
    int tid = threadIdx.x;
    int tx = tid & 15, ty = tid >> 4;
    int bm = blockIdx.y * 128, bn = blockIdx.x * 128;
    float acc[8][8] = {};
    for (int k0 = 0; k0 < K; k0 += 8){
        #pragma unroll
        for (int i = 0; i < 4; i++){
            int e = tid + i*256;
            int m  = e >> 3, kk  = e & 7;
            As[kk][m]  = (k0 + kk  < K) ? A[(size_t)(bm + m)*K + k0 + kk] : 0.f;
            int kk2 = e >> 7, nn = e & 127;
            Bs[kk2][nn] = (k0 + kk2 < K) ? Bw[(size_t)(k0 + kk2)*N + bn + nn] : 0.f;
        }
        __syncthreads();
        #pragma unroll
        for (int kk = 0; kk < 8; kk++){
            float a[8], b[8];
            *(float4*)&a[0] = *(const float4*)&As[kk][ty*8];
            *(float4*)&a[4] = *(const float4*)&As[kk][ty*8 + 4];
            *(float4*)&b[0] = *(const float4*)&Bs[kk][tx*8];
            *(float4*)&b[4] = *(const float4*)&Bs[kk][tx*8 + 4];
            #pragma unroll
            for (int i = 0; i < 8; i++)
                #pragma unroll
                for (int j = 0; j < 8; j++)
                    acc[i][j] += a[i]*b[j];
        }
        __syncthreads();
    }
    #pragma unroll
    for (int i = 0; i < 8; i++){
        size_t row = bm + ty*8 + i;
        *(float4*)&C[row*N + bn + tx*8]     = *(float4*)&acc[i][0];
        *(float4*)&C[row*N + bn + tx*8 + 4] = *(float4*)&acc[i][4];
    }
}

// ---------------- GCN aggregate: CSR gather, warp(s) per dst node ----------------
// y[d] = sum_{e in CSR(d)} w_e * XW[src_e] + dinv[d]^2 * XW[d] + bias
__global__ void k_aggregate(const float* __restrict__ bias, int ntot, int f, int wpn){
    int gw = (blockIdx.x*blockDim.x + threadIdx.x) >> 5;
    int lane = threadIdx.x & 31;
    int node = gw / wpn;
    if (node >= ntot) return;
    int fb = (gw % wpn)*128 + lane*4;
    int r0 = g_ROW[node];
    int cnt = g_CNT[node];
    float ax = 0.f, ay = 0.f, az = 0.f, aw = 0.f;
    for (int e = r0; e < r0 + cnt; e++){
        int s = g_CSRC[e];
        float w = g_CW[e];
        float4 v = *(const float4*)&g_XW[(size_t)s*f + fb];
        ax += w*v.x; ay += w*v.y; az += w*v.z; aw += w*v.w;
    }
    float di = g_DINV[node];
    float c = di*di;
    float4 sv = *(const float4*)&g_XW[(size_t)node*f + fb];
    float4 bv = *(const float4*)&bias[fb];
    float4 o = { ax + c*sv.x + bv.x, ay + c*sv.y + bv.y,
                 az + c*sv.z + bv.z, aw + c*sv.w + bv.w };
    *(float4*)&g_AGG[(size_t)node*f + fb] = o;
}

// ---------------- GraphNorm one-pass stats (sum + sumsq) ----------------
__global__ void k_stats(int n, int f){
    int g = blockIdx.x, fi = threadIdx.x;
    int ch = (n + gridDim.y - 1)/gridDim.y;
    int s0 = blockIdx.y*ch, s1 = min(s0 + ch, n);
    float s = 0.f, s2 = 0.f;
    const float* base = g_AGG + (size_t)g*n*f + fi;
    for (int i = s0; i < s1; i++){
        float v = base[(size_t)i*f];
        s += v; s2 += v*v;
    }
    atomicAdd(&g_STATS[g*f + fi], s);
    atomicAdd(&g_STATS[NG*256 + g*f + fi], s2);
}
__global__ void k_finstats(const float* __restrict__ ga, int n, int f){
    int i = blockIdx.x*blockDim.x + threadIdx.x;
    if (i >= NG*f) return;
    float inv_n = 1.f/(float)n;
    float mu = g_STATS[i]*inv_n;
    float m2 = g_STATS[NG*256 + i]*inv_n;
    float a = ga[i % f];
    float var = m2 - mu*mu*a*(2.f - a);   // mean((x - a*mu)^2)
    g_STATS[i] = mu;
    g_STATS[NG*256 + i] = rsqrtf(fmaxf(var, 0.f) + EPSN);
}

// ---------------- normalize + relu + topk score ----------------
__global__ void k_norm_apply(const float* __restrict__ gw, const float* __restrict__ gb,
                             const float* __restrict__ ga, const float* __restrict__ pw,
                             int n, int f){
    int node = blockIdx.x, fi = threadIdx.x;
    int g = node / n;
    size_t off = (size_t)node*f + fi;
    float mu = g_STATS[g*f + fi], rs = g_STATS[NG*256 + g*f + fi];
    float x = gw[fi]*(g_AGG[off] - ga[fi]*mu)*rs + gb[fi];
    x = fmaxf(x, 0.f);
    g_AGG[off] = x;
    __shared__ float sd[256], sw2[256];
    float p = pw[fi];
    sd[fi] = x*p; sw2[fi] = p*p;
    __syncthreads();
    for (int st = blockDim.x >> 1; st > 0; st >>= 1){
        if (fi < st){ sd[fi] += sd[fi+st]; sw2[fi] += sw2[fi+st]; }
        __syncthreads();
    }
    if (fi == 0) g_SCORE[node] = tanhf(sd[0]*rsqrtf(sw2[0]));
}

// ---------------- per-graph exact top-k (radix select + index-order compaction) ----
__global__ void k_topk(int n, int k, int nxt){
    __shared__ unsigned keys[4096];
    __shared__ int hist[256];
    __shared__ unsigned sh_prefix;
    __shared__ int sh_rem;
    __shared__ int sg[512], se[512];
    __shared__ int base_g, base_e;

    int g = blockIdx.x;
    int tid = threadIdx.x;
    if (g == 0 && tid == 0) g_ECNT[nxt] = 0;   // reset append counter for remap
    const float* sc = g_SCORE + (size_t)g*n;

    for (int i = tid; i < n; i += blockDim.x){
        unsigned u = __float_as_uint(sc[i]);
        u = (u & 0x80000000u) ? ~u : (u | 0x80000000u);
        keys[i] = u;
    }
    if (tid == 0){ sh_prefix = 0u; sh_rem = k; }
    __syncthreads();

    for (int shift = 24; shift >= 0; shift -= 8){
        for (int i = tid; i < 256; i += blockDim.x) hist[i] = 0;
        __syncthreads();
        unsigned pmask = (shift == 24) ? 0u : (0xFFFFFFFFu << (shift + 8));
        unsigned pref = sh_prefix;
        for (int i = tid; i < n; i += blockDim.x){
            unsigned u = keys[i];
            if ((u & pmask) == pref) atomicAdd(&hist[(u >> shift) & 0xFF], 1);
        }
        __syncthreads();
        if (tid == 0){
            int rem = sh_rem, b;
            for (b = 255; b >= 0; b--){
                if (rem <= hist[b]) break;
                rem -= hist[b];
            }
            sh_prefix |= ((unsigned)b) << shift;
            sh_rem = rem;
        }
        __syncthreads();
    }
    unsigned thr = sh_prefix;
    int need = sh_rem;
    if (tid == 0){ base_g = 0; base_e = 0; }
    __syncthreads();

    for (int c0 = 0; c0 < n; c0 += blockDim.x){
        int i = c0 + tid;
        int gf = 0, ef = 0;
        if (i < n){
            unsigned u = keys[i];
            gf = (u > thr);
            ef = (u == thr);
        }
        sg[tid] = gf; se[tid] = ef;
        __syncthreads();
        for (int st = 1; st < blockDim.x; st <<= 1){
            int vg = 0, ve = 0;
            if (tid >= st){ vg = sg[tid-st]; ve = se[tid-st]; }
            __syncthreads();
            sg[tid] += vg; se[tid] += ve;
            __syncthreads();
        }
        if (i < n){
            int g_before = base_g + sg[tid] - gf;
            int e_before = base_e + se[tid] - ef;
            bool kept = gf || (ef && (e_before < need));
            int oldg = g*n + i;
            if (kept){
                int newlocal = g_before + min(e_before, need);
                int newglobal = g*k + newlocal;
                g_MAP[oldg]        = newglobal;
                g_PERMG[newglobal] = oldg;
                g_GATE[newglobal]  = sc[i];
            } else {
                g_MAP[oldg] = -1;
            }
        }
        __syncthreads();
        if (tid == 0){ base_g += sg[blockDim.x-1]; base_e += se[blockDim.x-1]; }
        __syncthreads();
    }
}

// ---------------- gather compacted, gated nodes ----------------
__global__ void k_gather(int tot_new, int f){
    int per = f >> 2;
    size_t idx = (size_t)blockIdx.x*blockDim.x + threadIdx.x;
    if (idx >= (size_t)tot_new*per) return;
    int j  = (int)(idx / per);
    int fc = (int)(idx % per)*4;
    int old = g_PERMG[j];
    float gv = g_GATE[j];
    float4 v = *(const float4*)&g_AGG[(size_t)old*f + fc];
    float4 o = {v.x*gv, v.y*gv, v.z*gv, v.w*gv};
    *(float4*)&g_X[(size_t)j*f + fc] = o;
}

// ---------------- remap + compact edges for next layer ----------------
__global__ void k_remap(int cur){
    int e = blockIdx.x*blockDim.x + threadIdx.x;
    if (e >= g_ECNT[cur]) return;
    int s = g_MAP[g_ESRC[cur][e]];
    int d = g_MAP[g_EDST[cur][e]];
    if (s >= 0 && d >= 0){
        int p = atomicAdd(&g_ECNT[cur^1], 1);
        g_ESRC[cur^1][p] = s;
        g_EDST[cur^1][p] = d;
    }
}

// ---------------- readout ----------------
__global__ void k_readout(){
    int gg = blockIdx.x;
    int f  = threadIdx.x;
    const float* base = g_X + (size_t)gg*512*256;
    float s = 0.f, mx = -INFINITY;
    for (int i = 0; i < 512; i++){
        float v = base[(size_t)i*256 + f];
        s += v;
        mx = fmaxf(mx, v);
    }
    g_PMEAN[gg*256 + f] = s*(1.f/512.f);
    g_PMAX [gg*256 + f] = mx;
}

__global__ void k_final(float* __restrict__ out){
    int idx = blockIdx.x*blockDim.x + threadIdx.x;
    if (idx >= BATCH*512) return;
    int b = idx / 512, c = idx % 512;
    float acc = 0.f;
    if (c < 256){
        for (int t = 0; t < TS; t++) acc += g_PMEAN[(t*BATCH + b)*256 + c];
    } else {
        for (int t = 0; t < TS; t++) acc += g_PMAX[(t*BATCH + b)*256 + (c-256)];
    }
    out[idx] = acc*(1.f/(float)TS);
}

// ---------------- host orchestration ----------------
extern "C" void kernel_launch(void* const* d_in, const int* in_sizes, int n_in,
                              void* d_out, int out_size){
    const float* x_seq = (const float*)d_in[0];
    const int*   ei    = (const int*)  d_in[1];
    const float* W [3] = {(const float*)d_in[2],  (const float*)d_in[4],  (const float*)d_in[6]};
    const float* bb[3] = {(const float*)d_in[3],  (const float*)d_in[5],  (const float*)d_in[7]};
    const float* gw[3] = {(const float*)d_in[8],  (const float*)d_in[11], (const float*)d_in[14]};
    const float* gb[3] = {(const float*)d_in[9],  (const float*)d_in[12], (const float*)d_in[15]};
    const float* ga[3] = {(const float*)d_in[10], (const float*)d_in[13], (const float*)d_in[16]};
    const float* pw[3] = {(const float*)d_in[17], (const float*)d_in[18], (const float*)d_in[19]};
    float* out = (float*)d_out;

    float *pXW, *pX, *pSTATS;
    int *pCNT, *pCUR;
    cudaGetSymbolAddress((void**)&pXW,    g_XW);
    cudaGetSymbolAddress((void**)&pX,     g_X);
    cudaGetSymbolAddress((void**)&pSTATS, g_STATS);
    cudaGetSymbolAddress((void**)&pCNT,   g_CNT);
    cudaGetSymbolAddress((void**)&pCUR,   g_CUR);

    k_edge_init<<<NEDGE/256, 256>>>(ei);

    const int nin [3] = {4096, 2048, 1024};
    const int nk  [3] = {2048, 1024, 512};
    const int fin [3] = {100, 128, 128};
    const int fout[3] = {128, 128, 256};

    const float* A = x_seq;
    for (int l = 0; l < 3; l++){
        int n = nin[l], k = nk[l], fi = fin[l], fo = fout[l];
        int ntot = NG * n;
        int cur = l & 1, nxt = cur ^ 1;
        int nb = ntot / 512;
        int wpn = fo / 128;

        // CSR build
        k_zeroi<<<(ntot + 255)/256, 256>>>(pCNT, ntot);
        k_zeroi<<<(ntot + 255)/256, 256>>>(pCUR, ntot);
        k_zero <<<64, 256>>>(pSTATS, (size_t)2*NG*256);
        k_count<<<NEDGE/256, 256>>>(cur);
        k_scan1<<<nb, 512>>>(ntot);
        k_scan2<<<1, 1024>>>(nb);
        k_scan3<<<nb, 512>>>(ntot);
        k_dinv <<<(ntot + 255)/256, 256>>>(ntot);
        k_fill <<<NEDGE/256, 256>>>(cur);

        // GCN
        k_sgemm<<<dim3(fo/128, ntot/128), 256>>>(A, W[l], pXW, ntot, fo, fi);
        k_aggregate<<<ntot*wpn/8, 256>>>(bb[l], ntot, fo, wpn);

        // GraphNorm + ReLU + score
        k_stats<<<dim3(NG, 16), fo>>>(n, fo);
        k_finstats<<<(NG*fo + 255)/256, 256>>>(ga[l], n, fo);
        k_norm_apply<<<ntot, fo>>>(gw[l], gb[l], ga[l], pw[l], n, fo);

        // TopK pool
        k_topk<<<NG, 512>>>(n, k, nxt);
        int tot_new = NG * k;
        k_gather<<<(int)(((size_t)tot_new*(fo/4) + 255)/256), 256>>>(tot_new, fo);
        if (l < 2) k_remap<<<NEDGE/256, 256>>>(cur);

        A = pX;
    }

    k_readout<<<NG, 256>>>();
    k_final<<<(BATCH*512 + 255)/256, 256>>>(out);
}

// round 4
// speedup vs baseline: 1.9526x; 1.1721x over previous
#include <cuda_runtime.h>
#include <math.h>
#include <stdint.h>

// ---------------- problem constants ----------------
#define TS     8
#define BATCH  16
#define NPG    4096
#define NEDGE  (TS*BATCH*32768)   // 4,194,304 edges (all timesteps, layer 1)
#define NG     (TS*BATCH)         // 128 graphs
#define EPSN   1e-5f
#define MAXN   524288

// ---------------- static device scratch ----------------
__device__ float g_XW [67108864];   // x @ W        (max 524288 x 128)
__device__ float g_AGG[67108864];   // gcn out / normalized x
__device__ float g_X  [33554432];   // compacted layer input
__device__ float g_DINV[MAXN];
__device__ float g_SCORE[MAXN];
__device__ int   g_MAP [MAXN];
__device__ int   g_PERMG[262144];
__device__ float g_GATE [262144];
__device__ int   g_CNT[MAXN];       // in-degree counts
__device__ int   g_CUR[MAXN];       // fill cursors
__device__ int   g_ROW[MAXN];       // CSR row starts (exclusive scan)
__device__ int   g_BSUM[1024];
__device__ int   g_CSRC[NEDGE];     // CSR: src node per slot
__device__ float g_CW [NEDGE];      // CSR: edge coefficient dinv[s]*dinv[d]
__device__ int   g_ESRC[2][NEDGE];  // double-buffered compacted edge lists
__device__ int   g_EDST[2][NEDGE];
__device__ int   g_ECNT[2];
__device__ float g_STATS[2*NG*256]; // [0]: sum->mu, [NG*256]: sumsq->rsigma
__device__ float g_PMEAN[NG*256];
__device__ float g_PMAX [NG*256];

// ---------------- utility ----------------
__global__ void k_zero(float* p, size_t cnt){
    size_t i = (size_t)blockIdx.x*blockDim.x + threadIdx.x;
    size_t stride = (size_t)gridDim.x*blockDim.x;
    for (; i < cnt; i += stride) p[i] = 0.f;
}
__global__ void k_zeroi(int* p, int cnt){
    int i = blockIdx.x*blockDim.x + threadIdx.x;
    if (i < cnt) p[i] = 0;
}

__global__ void k_edge_init(const int* __restrict__ ei){
    int idx = blockIdx.x*blockDim.x + threadIdx.x;
    if (idx == 0){ g_ECNT[0] = NEDGE; g_ECNT[1] = 0; }
    if (idx >= NEDGE) return;
    const int E = 32768*BATCH;         // 524288 edges per timestep
    int t = idx / E, e = idx % E;
    int base = t * (BATCH*NPG);
    g_ESRC[0][idx] = ei[(size_t)t*2*E + e]     + base;
    g_EDST[0][idx] = ei[(size_t)t*2*E + E + e] + base;
}

// ---------------- CSR build ----------------
__global__ void k_count(int cur){
    int e = blockIdx.x*blockDim.x + threadIdx.x;
    if (e >= g_ECNT[cur]) return;
    atomicAdd(&g_CNT[g_EDST[cur][e]], 1);
}

__global__ void k_scan1(int n){
    __shared__ int sh[512];
    int i = blockIdx.x*512 + threadIdx.x;
    int v = (i < n) ? g_CNT[i] : 0;
    sh[threadIdx.x] = v;
    __syncthreads();
    for (int st = 1; st < 512; st <<= 1){
        int t = (threadIdx.x >= st) ? sh[threadIdx.x - st] : 0;
        __syncthreads();
        sh[threadIdx.x] += t;
        __syncthreads();
    }
    if (i < n) g_ROW[i] = sh[threadIdx.x] - v;
    if (threadIdx.x == 511) g_BSUM[blockIdx.x] = sh[511];
}
__global__ void k_scan2(int nb){
    __shared__ int sh[1024];
    int v = (threadIdx.x < nb) ? g_BSUM[threadIdx.x] : 0;
    sh[threadIdx.x] = v;
    __syncthreads();
    for (int st = 1; st < 1024; st <<= 1){
        int t = (threadIdx.x >= st) ? sh[threadIdx.x - st] : 0;
        __syncthreads();
        sh[threadIdx.x] += t;
        __syncthreads();
    }
    if (threadIdx.x < nb) g_BSUM[threadIdx.x] = sh[threadIdx.x] - v;
}
__global__ void k_scan3(int n){
    int i = blockIdx.x*512 + threadIdx.x;
    if (i < n) g_ROW[i] += g_BSUM[blockIdx.x];
}

__global__ void k_dinv(int ntot){
    int i = blockIdx.x*blockDim.x + threadIdx.x;
    if (i < ntot) g_DINV[i] = rsqrtf(1.f + (float)g_CNT[i]);
}

__global__ void k_fill(int cur){
    int e = blockIdx.x*blockDim.x + threadIdx.x;
    if (e >= g_ECNT[cur]) return;
    int s = g_ESRC[cur][e], d = g_EDST[cur][e];
    int slot = g_ROW[d] + atomicAdd(&g_CUR[d], 1);
    g_CSRC[slot] = s;
    g_CW[slot]   = g_DINV[s]*g_DINV[d];
}

// ---------------- tf32-split tensor-core GEMM (mma.sync, portable PTX) ----------
// C[M,N] = A[M,K] @ W[K,N]. Tile 128x128, K chunk 32. 8 warps: 4(m) x 2(n).
// Each warp: 32(m) x 64(n) = 2 m-atoms x 8 n-atoms of m16n8k8.
// 3-term tf32 split: hi*hi + lo*hi + hi*lo (residual ~2^-22).
#define AS_STRIDE 36
#define BS_STRIDE 136

__device__ __forceinline__ uint32_t f2tf32(float v){
    uint32_t u;
    asm("cvt.rna.tf32.f32 %0, %1;" : "=r"(u) : "f"(v));
    return u;
}
__device__ __forceinline__ void mma8(float* d, uint32_t a0, uint32_t a1, uint32_t a2, uint32_t a3,
                                     uint32_t b0, uint32_t b1){
    asm volatile("mma.sync.aligned.m16n8k8.row.col.f32.tf32.tf32.f32 "
        "{%0,%1,%2,%3}, {%4,%5,%6,%7}, {%8,%9}, {%0,%1,%2,%3};"
        : "+f"(d[0]), "+f"(d[1]), "+f"(d[2]), "+f"(d[3])
        : "r"(a0), "r"(a1), "r"(a2), "r"(a3), "r"(b0), "r"(b1));
}

__global__ void __launch_bounds__(256) k_gemm_tc(const float* __restrict__ A,
                                                 const float* __restrict__ W,
                                                 float* __restrict__ C,
                                                 int M, int N, int K){
    __shared__ float As[128*AS_STRIDE];
    __shared__ float Bs[32*BS_STRIDE];
    const int tid = threadIdx.x, lane = tid & 31, wid = tid >> 5;
    const int wm = (wid >> 1)*32, wn = (wid & 1)*64;
    const int bm = blockIdx.y*128, bn = blockIdx.x*128;
    const int g4 = lane >> 2, t4 = lane & 3;

    float acc[2][8][4] = {};

    const int nch = (K + 31)/32;
    for (int kc = 0; kc < nch; kc++){
        const int k0 = kc*32;
        // stage A chunk [128 x 32]
        #pragma unroll
        for (int it = 0; it < 16; it++){
            int idx = it*256 + tid;
            int col = idx & 31, row = idx >> 5;
            int kg = k0 + col;
            As[row*AS_STRIDE + col] = (kg < K) ? A[(size_t)(bm+row)*K + kg] : 0.f;
        }
        // stage B chunk [32 x 128]
        #pragma unroll
        for (int it = 0; it < 16; it++){
            int idx = it*256 + tid;
            int nc = idx & 127, kr = idx >> 7;
            int kg = k0 + kr;
            Bs[kr*BS_STRIDE + nc] = (kg < K) ? W[(size_t)kg*N + bn + nc] : 0.f;
        }
        __syncthreads();

        #pragma unroll
        for (int kk = 0; kk < 32; kk += 8){
            uint32_t ah[2][4], al[2][4];
            #pragma unroll
            for (int ma = 0; ma < 2; ma++){
                int r0 = wm + ma*16 + g4;
                int c0 = kk + t4;
                float v0 = As[r0*AS_STRIDE + c0];
                float v1 = As[(r0+8)*AS_STRIDE + c0];
                float v2 = As[r0*AS_STRIDE + c0 + 4];
                float v3 = As[(r0+8)*AS_STRIDE + c0 + 4];
                ah[ma][0] = f2tf32(v0); al[ma][0] = f2tf32(v0 - __uint_as_float(ah[ma][0]));
                ah[ma][1] = f2tf32(v1); al[ma][1] = f2tf32(v1 - __uint_as_float(ah[ma][1]));
                ah[ma][2] = f2tf32(v2); al[ma][2] = f2tf32(v2 - __uint_as_float(ah[ma][2]));
                ah[ma][3] = f2tf32(v3); al[ma][3] = f2tf32(v3 - __uint_as_float(ah[ma][3]));
            }
            #pragma unroll
            for (int jn = 0; jn < 8; jn++){
                int col = wn + jn*8 + g4;
                float w0 = Bs[(kk + t4)*BS_STRIDE + col];
                float w1 = Bs[(kk + 4 + t4)*BS_STRIDE + col];
                uint32_t bh0 = f2tf32(w0), bl0 = f2tf32(w0 - __uint_as_float(bh0));
                uint32_t bh1 = f2tf32(w1), bl1 = f2tf32(w1 - __uint_as_float(bh1));
                #pragma unroll
                for (int ma = 0; ma < 2; ma++){
                    mma8(acc[ma][jn], ah[ma][0], ah[ma][1], ah[ma][2], ah[ma][3], bh0, bh1);
                    mma8(acc[ma][jn], al[ma][0], al[ma][1], al[ma][2], al[ma][3], bh0, bh1);
                    mma8(acc[ma][jn], ah[ma][0], ah[ma][1], ah[ma][2], ah[ma][3], bl0, bl1);
                }
            }
        }
        __syncthreads();
    }

    // epilogue: c0,c1 -> (row, 2t),(row, 2t+1); c2,c3 -> row+8
    #pragma unroll
    for (int ma = 0; ma < 2; ma++){
        #pragma unroll
        for (int jn = 0; jn < 8; jn++){
            size_t row0 = (size_t)bm + wm + ma*16 + g4;
            size_t col  = (size_t)bn + wn + jn*8 + t4*2;
            float2 lo = { acc[ma][jn][0], acc[ma][jn][1] };
            float2 hi = { acc[ma][jn][2], acc[ma][jn][3] };
            *(float2*)&C[row0*N + col]     = lo;
            *(float2*)&C[(row0+8)*N + col] = hi;
        }
    }
}

// ---------------- GCN aggregate: CSR gather, warp(s) per dst node ----------------
__global__ void k_aggregate(const float* __restrict__ bias, int ntot, int f, int wpn){
    int gw = (blockIdx.x*blockDim.x + threadIdx.x) >> 5;
    int lane = threadIdx.x & 31;
    int node = gw / wpn;
    if (node >= ntot) return;
    int fb = (gw % wpn)*128 + lane*4;
    int r0 = g_ROW[node];
    int cnt = g_CNT[node];
    float ax = 0.f, ay = 0.f, az = 0.f, aw = 0.f;
    for (int e = r0; e < r0 + cnt; e++){
        int s = g_CSRC[e];
        float w = g_CW[e];
        float4 v = *(const float4*)&g_XW[(size_t)s*f + fb];
        ax += w*v.x; ay += w*v.y; az += w*v.z; aw += w*v.w;
    }
    float di = g_DINV[node];
    float c = di*di;
    float4 sv = *(const float4*)&g_XW[(size_t)node*f + fb];
    float4 bv = *(const float4*)&bias[fb];
    float4 o = { ax + c*sv.x + bv.x, ay + c*sv.y + bv.y,
                 az + c*sv.z + bv.z, aw + c*sv.w + bv.w };
    *(float4*)&g_AGG[(size_t)node*f + fb] = o;
}

// ---------------- GraphNorm one-pass stats (sum + sumsq) ----------------
__global__ void k_stats(int n, int f){
    int g = blockIdx.x, fi = threadIdx.x;
    int ch = (n + gridDim.y - 1)/gridDim.y;
    int s0 = blockIdx.y*ch, s1 = min(s0 + ch, n);
    float s = 0.f, s2 = 0.f;
    const float* base = g_AGG + (size_t)g*n*f + fi;
    for (int i = s0; i < s1; i++){
        float v = base[(size_t)i*f];
        s += v; s2 += v*v;
    }
    atomicAdd(&g_STATS[g*f + fi], s);
    atomicAdd(&g_STATS[NG*256 + g*f + fi], s2);
}
__global__ void k_finstats(const float* __restrict__ ga, int n, int f){
    int i = blockIdx.x*blockDim.x + threadIdx.x;
    if (i >= NG*f) return;
    float inv_n = 1.f/(float)n;
    float mu = g_STATS[i]*inv_n;
    float m2 = g_STATS[NG*256 + i]*inv_n;
    float a = ga[i % f];
    float var = m2 - mu*mu*a*(2.f - a);
    g_STATS[i] = mu;
    g_STATS[NG*256 + i] = rsqrtf(fmaxf(var, 0.f) + EPSN);
}

// ---------------- normalize + relu + topk score ----------------
__global__ void k_norm_apply(const float* __restrict__ gw, const float* __restrict__ gb,
                             const float* __restrict__ ga, const float* __restrict__ pw,
                             int n, int f){
    int node = blockIdx.x, fi = threadIdx.x;
    int g = node / n;
    size_t off = (size_t)node*f + fi;
    float mu = g_STATS[g*f + fi], rs = g_STATS[NG*256 + g*f + fi];
    float x = gw[fi]*(g_AGG[off] - ga[fi]*mu)*rs + gb[fi];
    x = fmaxf(x, 0.f);
    g_AGG[off] = x;
    __shared__ float sd[256], sw2[256];
    float p = pw[fi];
    sd[fi] = x*p; sw2[fi] = p*p;
    __syncthreads();
    for (int st = blockDim.x >> 1; st > 0; st >>= 1){
        if (fi < st){ sd[fi] += sd[fi+st]; sw2[fi] += sw2[fi+st]; }
        __syncthreads();
    }
    if (fi == 0) g_SCORE[node] = tanhf(sd[0]*rsqrtf(sw2[0]));
}

// ---------------- per-graph exact top-k ----------------
__global__ void k_topk(int n, int k, int nxt){
    __shared__ unsigned keys[4096];
    __shared__ int hist[256];
    __shared__ unsigned sh_prefix;
    __shared__ int sh_rem;
    __shared__ int sg[512], se[512];
    __shared__ int base_g, base_e;

    int g = blockIdx.x;
    int tid = threadIdx.x;
    if (g == 0 && tid == 0) g_ECNT[nxt] = 0;
    const float* sc = g_SCORE + (size_t)g*n;

    for (int i = tid; i < n; i += blockDim.x){
        unsigned u = __float_as_uint(sc[i]);
        u = (u & 0x80000000u) ? ~u : (u | 0x80000000u);
        keys[i] = u;
    }
    if (tid == 0){ sh_prefix = 0u; sh_rem = k; }
    __syncthreads();

    for (int shift = 24; shift >= 0; shift -= 8){
        for (int i = tid; i < 256; i += blockDim.x) hist[i] = 0;
        __syncthreads();
        unsigned pmask = (shift == 24) ? 0u : (0xFFFFFFFFu << (shift + 8));
        unsigned pref = sh_prefix;
        for (int i = tid; i < n; i += blockDim.x){
            unsigned u = keys[i];
            if ((u & pmask) == pref) atomicAdd(&hist[(u >> shift) & 0xFF], 1);
        }
        __syncthreads();
        if (tid == 0){
            int rem = sh_rem, b;
            for (b = 255; b >= 0; b--){
                if (rem <= hist[b]) break;
                rem -= hist[b];
            }
            sh_prefix |= ((unsigned)b) << shift;
            sh_rem = rem;
        }
        __syncthreads();
    }
    unsigned thr = sh_prefix;
    int need = sh_rem;
    if (tid == 0){ base_g = 0; base_e = 0; }
    __syncthreads();

    for (int c0 = 0; c0 < n; c0 += blockDim.x){
        int i = c0 + tid;
        int gf = 0, ef = 0;
        if (i < n){
            unsigned u = keys[i];
            gf = (u > thr);
            ef = (u == thr);
        }
        sg[tid] = gf; se[tid] = ef;
        __syncthreads();
        for (int st = 1; st < blockDim.x; st <<= 1){
            int vg = 0, ve = 0;
            if (tid >= st){ vg = sg[tid-st]; ve = se[tid-st]; }
            __syncthreads();
            sg[tid] += vg; se[tid] += ve;
            __syncthreads();
        }
        if (i < n){
            int g_before = base_g + sg[tid] - gf;
            int e_before = base_e + se[tid] - ef;
            bool kept = gf || (ef && (e_before < need));
            int oldg = g*n + i;
            if (kept){
                int newlocal = g_before + min(e_before, need);
                int newglobal = g*k + newlocal;
                g_MAP[oldg]        = newglobal;
                g_PERMG[newglobal] = oldg;
                g_GATE[newglobal]  = sc[i];
            } else {
                g_MAP[oldg] = -1;
            }
        }
        __syncthreads();
        if (tid == 0){ base_g += sg[blockDim.x-1]; base_e += se[blockDim.x-1]; }
        __syncthreads();
    }
}

// ---------------- gather compacted, gated nodes ----------------
__global__ void k_gather(int tot_new, int f){
    int per = f >> 2;
    size_t idx = (size_t)blockIdx.x*blockDim.x + threadIdx.x;
    if (idx >= (size_t)tot_new*per) return;
    int j  = (int)(idx / per);
    int fc = (int)(idx % per)*4;
    int old = g_PERMG[j];
    float gv = g_GATE[j];
    float4 v = *(const float4*)&g_AGG[(size_t)old*f + fc];
    float4 o = {v.x*gv, v.y*gv, v.z*gv, v.w*gv};
    *(float4*)&g_X[(size_t)j*f + fc] = o;
}

// ---------------- remap + compact edges for next layer ----------------
__global__ void k_remap(int cur){
    int e = blockIdx.x*blockDim.x + threadIdx.x;
    if (e >= g_ECNT[cur]) return;
    int s = g_MAP[g_ESRC[cur][e]];
    int d = g_MAP[g_EDST[cur][e]];
    if (s >= 0 && d >= 0){
        int p = atomicAdd(&g_ECNT[cur^1], 1);
        g_ESRC[cur^1][p] = s;
        g_EDST[cur^1][p] = d;
    }
}

// ---------------- readout ----------------
__global__ void k_readout(){
    int gg = blockIdx.x;
    int f  = threadIdx.x;
    const float* base = g_X + (size_t)gg*512*256;
    float s = 0.f, mx = -INFINITY;
    for (int i = 0; i < 512; i++){
        float v = base[(size_t)i*256 + f];
        s += v;
        mx = fmaxf(mx, v);
    }
    g_PMEAN[gg*256 + f] = s*(1.f/512.f);
    g_PMAX [gg*256 + f] = mx;
}

__global__ void k_final(float* __restrict__ out){
    int idx = blockIdx.x*blockDim.x + threadIdx.x;
    if (idx >= BATCH*512) return;
    int b = idx / 512, c = idx % 512;
    float acc = 0.f;
    if (c < 256){
        for (int t = 0; t < TS; t++) acc += g_PMEAN[(t*BATCH + b)*256 + c];
    } else {
        for (int t = 0; t < TS; t++) acc += g_PMAX[(t*BATCH + b)*256 + (c-256)];
    }
    out[idx] = acc*(1.f/(float)TS);
}

// ---------------- host orchestration ----------------
extern "C" void kernel_launch(void* const* d_in, const int* in_sizes, int n_in,
                              void* d_out, int out_size){
    const float* x_seq = (const float*)d_in[0];
    const int*   ei    = (const int*)  d_in[1];
    const float* W [3] = {(const float*)d_in[2],  (const float*)d_in[4],  (const float*)d_in[6]};
    const float* bb[3] = {(const float*)d_in[3],  (const float*)d_in[5],  (const float*)d_in[7]};
    const float* gw[3] = {(const float*)d_in[8],  (const float*)d_in[11], (const float*)d_in[14]};
    const float* gb[3] = {(const float*)d_in[9],  (const float*)d_in[12], (const float*)d_in[15]};
    const float* ga[3] = {(const float*)d_in[10], (const float*)d_in[13], (const float*)d_in[16]};
    const float* pw[3] = {(const float*)d_in[17], (const float*)d_in[18], (const float*)d_in[19]};
    float* out = (float*)d_out;

    float *pXW, *pX, *pSTATS;
    int *pCNT, *pCUR;
    cudaGetSymbolAddress((void**)&pXW,    g_XW);
    cudaGetSymbolAddress((void**)&pX,     g_X);
    cudaGetSymbolAddress((void**)&pSTATS, g_STATS);
    cudaGetSymbolAddress((void**)&pCNT,   g_CNT);
    cudaGetSymbolAddress((void**)&pCUR,   g_CUR);

    k_edge_init<<<NEDGE/256, 256>>>(ei);

    const int nin [3] = {4096, 2048, 1024};
    const int nk  [3] = {2048, 1024, 512};
    const int fin [3] = {100, 128, 128};
    const int fout[3] = {128, 128, 256};

    const float* A = x_seq;
    for (int l = 0; l < 3; l++){
        int n = nin[l], k = nk[l], fi = fin[l], fo = fout[l];
        int ntot = NG * n;
        int cur = l & 1, nxt = cur ^ 1;
        int nb = ntot / 512;
        int wpn = fo / 128;

        // CSR build
        k_zeroi<<<(ntot + 255)/256, 256>>>(pCNT, ntot);
        k_zeroi<<<(ntot + 255)/256, 256>>>(pCUR, ntot);
        k_zero <<<64, 256>>>(pSTATS, (size_t)2*NG*256);
        k_count<<<NEDGE/256, 256>>>(cur);
        k_scan1<<<nb, 512>>>(ntot);
        k_scan2<<<1, 1024>>>(nb);
        k_scan3<<<nb, 512>>>(ntot);
        k_dinv <<<(ntot + 255)/256, 256>>>(ntot);
        k_fill <<<NEDGE/256, 256>>>(cur);

        // GCN: tensor-core tf32-split GEMM + CSR aggregate
        k_gemm_tc<<<dim3(fo/128, ntot/128), 256>>>(A, W[l], pXW, ntot, fo, fi);
        k_aggregate<<<ntot*wpn/8, 256>>>(bb[l], ntot, fo, wpn);

        // GraphNorm + ReLU + score
        k_stats<<<dim3(NG, 16), fo>>>(n, fo);
        k_finstats<<<(NG*fo + 255)/256, 256>>>(ga[l], n, fo);
        k_norm_apply<<<ntot, fo>>>(gw[l], gb[l], ga[l], pw[l], n, fo);

        // TopK pool
        k_topk<<<NG, 512>>>(n, k, nxt);
        int tot_new = NG * k;
        k_gather<<<(int)(((size_t)tot_new*(fo/4) + 255)/256), 256>>>(tot_new, fo);
        if (l < 2) k_remap<<<NEDGE/256, 256>>>(cur);

        A = pX;
    }

    k_readout<<<NG, 256>>>();
    k_final<<<(BATCH*512 + 255)/256, 256>>>(out);
}

// round 5
// speedup vs baseline: 1.9961x; 1.0223x over previous
#include <cuda_runtime.h>
#include <math.h>
#include <stdint.h>

// ---------------- problem constants ----------------
#define TS     8
#define BATCH  16
#define NPG    4096
#define NEDGE  (TS*BATCH*32768)   // 4,194,304 edges (all timesteps, layer 1)
#define NG     (TS*BATCH)         // 128 graphs
#define EPSN   1e-5f
#define MAXN   524288

// ---------------- static device scratch ----------------
__device__ float g_S  [67108864];   // aggregated input  S = A_norm * X
__device__ float g_AGG[67108864];   // gcn output Y = S*W + b
__device__ float g_X  [33554432];   // compacted layer input (normalized+gated)
__device__ float g_DINV[MAXN];
__device__ float g_SCORE[MAXN];
__device__ int   g_MAP [MAXN];
__device__ int   g_PERMG[262144];
__device__ float g_GATE [262144];
__device__ int   g_CNT[MAXN];       // in-degree counts
__device__ int   g_CUR[MAXN];       // fill cursors
__device__ int   g_ROW[MAXN];       // CSR row starts
__device__ int   g_BSUM[1024];
__device__ int   g_CSRC[NEDGE];     // CSR src per slot
__device__ float g_CW [NEDGE];      // CSR coef dinv[s]*dinv[d]
__device__ int   g_ESRC[2][NEDGE];
__device__ int   g_EDST[2][NEDGE];
__device__ int   g_ECNT[2];
__device__ float g_SP1[16*NG*256];  // stats partial sums
__device__ float g_SP2[16*NG*256];  // stats partial sumsq
__device__ float g_MU [NG*256];
__device__ float g_RS [NG*256];
__device__ float g_IPN;             // 1/||pw||
__device__ float g_PMEAN[NG*256];
__device__ float g_PMAX [NG*256];

// ---------------- utility ----------------
__global__ void k_zero2i(int* a, int* b, int cnt){
    int i = blockIdx.x*blockDim.x + threadIdx.x;
    if (i < cnt){ a[i] = 0; b[i] = 0; }
}

__global__ void k_edge_init(const int* __restrict__ ei){
    int idx = blockIdx.x*blockDim.x + threadIdx.x;
    if (idx == 0){ g_ECNT[0] = NEDGE; g_ECNT[1] = 0; }
    if (idx >= NEDGE) return;
    const int E = 32768*BATCH;
    int t = idx / E, e = idx % E;
    int base = t * (BATCH*NPG);
    int s = ei[(size_t)t*2*E + e]     + base;
    int d = ei[(size_t)t*2*E + E + e] + base;
    g_ESRC[0][idx] = s;
    g_EDST[0][idx] = d;
    atomicAdd(&g_CNT[d], 1);          // fused in-degree count (layer 1)
}

// ---------------- CSR build ----------------
__global__ void k_scan1(int n){
    __shared__ int sh[512];
    int i = blockIdx.x*512 + threadIdx.x;
    int v = (i < n) ? g_CNT[i] : 0;
    sh[threadIdx.x] = v;
    __syncthreads();
    for (int st = 1; st < 512; st <<= 1){
        int t = (threadIdx.x >= st) ? sh[threadIdx.x - st] : 0;
        __syncthreads();
        sh[threadIdx.x] += t;
        __syncthreads();
    }
    if (i < n) g_ROW[i] = sh[threadIdx.x] - v;
    if (threadIdx.x == 511) g_BSUM[blockIdx.x] = sh[511];
}
__global__ void k_scan2(int nb){
    __shared__ int sh[1024];
    int v = (threadIdx.x < nb) ? g_BSUM[threadIdx.x] : 0;
    sh[threadIdx.x] = v;
    __syncthreads();
    for (int st = 1; st < 1024; st <<= 1){
        int t = (threadIdx.x >= st) ? sh[threadIdx.x - st] : 0;
        __syncthreads();
        sh[threadIdx.x] += t;
        __syncthreads();
    }
    if (threadIdx.x < nb) g_BSUM[threadIdx.x] = sh[threadIdx.x] - v;
}
__global__ void k_scan3d(int n){   // scan finish + dinv fused
    int i = blockIdx.x*512 + threadIdx.x;
    if (i < n){
        g_ROW[i] += g_BSUM[blockIdx.x];
        g_DINV[i] = rsqrtf(1.f + (float)g_CNT[i]);
    }
}

__global__ void k_fill(int cur){
    int e = blockIdx.x*blockDim.x + threadIdx.x;
    if (e >= g_ECNT[cur]) return;
    int s = g_ESRC[cur][e], d = g_EDST[cur][e];
    int slot = g_ROW[d] + atomicAdd(&g_CUR[d], 1);
    g_CSRC[slot] = s;
    g_CW[slot]   = g_DINV[s]*g_DINV[d];
}

// ---------------- aggregate-first: S[d] = sum w_e X[s] + dinv[d]^2 X[d] ----------
__global__ void k_aggregate(const float* __restrict__ X, int ntot, int f, int wpn){
    int gw = (blockIdx.x*blockDim.x + threadIdx.x) >> 5;
    int lane = threadIdx.x & 31;
    int node = gw / wpn;
    if (node >= ntot) return;
    int fb = (gw % wpn)*128 + lane*4;
    if (fb >= f) return;
    int r0 = g_ROW[node];
    int cnt = g_CNT[node];
    float ax = 0.f, ay = 0.f, az = 0.f, aw = 0.f;
    for (int e = r0; e < r0 + cnt; e++){
        int s = g_CSRC[e];
        float w = g_CW[e];
        float4 v = *(const float4*)&X[(size_t)s*f + fb];
        ax += w*v.x; ay += w*v.y; az += w*v.z; aw += w*v.w;
    }
    float di = g_DINV[node];
    float c = di*di;
    float4 sv = *(const float4*)&X[(size_t)node*f + fb];
    float4 o = { ax + c*sv.x, ay + c*sv.y, az + c*sv.z, aw + c*sv.w };
    *(float4*)&g_S[(size_t)node*f + fb] = o;
}

// ---------------- tf32-split tensor-core GEMM + fused bias ----------------
// C[M,N] = A[M,K] @ W[K,N] + bias. Tile 128x128, K chunk 32, hi/lo pre-split in smem.
#define AS_STRIDE 36
#define BS_STRIDE 136
#define SM_AH 0
#define SM_AL (128*AS_STRIDE)
#define SM_BH (2*128*AS_STRIDE)
#define SM_BL (2*128*AS_STRIDE + 32*BS_STRIDE)
#define SM_TOT ((2*128*AS_STRIDE + 2*32*BS_STRIDE)*4)

__device__ __forceinline__ float f2hi(float v){
    float h;
    asm("cvt.rna.tf32.f32 %0, %1;" : "=f"(h) : "f"(v));
    return h;
}
__device__ __forceinline__ void mma8(float* d, uint32_t a0, uint32_t a1, uint32_t a2, uint32_t a3,
                                     uint32_t b0, uint32_t b1){
    asm volatile("mma.sync.aligned.m16n8k8.row.col.f32.tf32.tf32.f32 "
        "{%0,%1,%2,%3}, {%4,%5,%6,%7}, {%8,%9}, {%0,%1,%2,%3};"
        : "+f"(d[0]), "+f"(d[1]), "+f"(d[2]), "+f"(d[3])
        : "r"(a0), "r"(a1), "r"(a2), "r"(a3), "r"(b0), "r"(b1));
}

__global__ void __launch_bounds__(256) k_gemm_tc(const float* __restrict__ A,
                                                 const float* __restrict__ W,
                                                 const float* __restrict__ bias,
                                                 float* __restrict__ C,
                                                 int M, int N, int K){
    extern __shared__ float sm[];
    float* Ah = sm + SM_AH;
    float* Al = sm + SM_AL;
    float* Bh = sm + SM_BH;
    float* Bl = sm + SM_BL;
    const int tid = threadIdx.x, lane = tid & 31, wid = tid >> 5;
    const int wm = (wid >> 1)*32, wn = (wid & 1)*64;
    const int bm = blockIdx.y*128, bn = blockIdx.x*128;
    const int g4 = lane >> 2, t4 = lane & 3;

    float acc[2][8][4] = {};

    const int nch = (K + 31)/32;
    for (int kc = 0; kc < nch; kc++){
        const int k0 = kc*32;
        #pragma unroll
        for (int it = 0; it < 16; it++){
            int idx = it*256 + tid;
            int col = idx & 31, row = idx >> 5;
            int kg = k0 + col;
            float v = (kg < K) ? A[(size_t)(bm+row)*K + kg] : 0.f;
            float h = f2hi(v);
            Ah[row*AS_STRIDE + col] = h;
            Al[row*AS_STRIDE + col] = v - h;
        }
        #pragma unroll
        for (int it = 0; it < 16; it++){
            int idx = it*256 + tid;
            int nc = idx & 127, kr = idx >> 7;
            int kg = k0 + kr;
            float v = (kg < K) ? W[(size_t)kg*N + bn + nc] : 0.f;
            float h = f2hi(v);
            Bh[kr*BS_STRIDE + nc] = h;
            Bl[kr*BS_STRIDE + nc] = v - h;
        }
        __syncthreads();

        #pragma unroll
        for (int kk = 0; kk < 32; kk += 8){
            uint32_t ah[2][4], al[2][4];
            #pragma unroll
            for (int ma = 0; ma < 2; ma++){
                int r0 = (wm + ma*16 + g4)*AS_STRIDE;
                int c0 = kk + t4;
                ah[ma][0] = __float_as_uint(Ah[r0 + c0]);
                ah[ma][1] = __float_as_uint(Ah[r0 + 8*AS_STRIDE + c0]);
                ah[ma][2] = __float_as_uint(Ah[r0 + c0 + 4]);
                ah[ma][3] = __float_as_uint(Ah[r0 + 8*AS_STRIDE + c0 + 4]);
                al[ma][0] = __float_as_uint(Al[r0 + c0]);
                al[ma][1] = __float_as_uint(Al[r0 + 8*AS_STRIDE + c0]);
                al[ma][2] = __float_as_uint(Al[r0 + c0 + 4]);
                al[ma][3] = __float_as_uint(Al[r0 + 8*AS_STRIDE + c0 + 4]);
            }
            #pragma unroll
            for (int jn = 0; jn < 8; jn++){
                int col = wn + jn*8 + g4;
                uint32_t bh0 = __float_as_uint(Bh[(kk + t4)*BS_STRIDE + col]);
                uint32_t bh1 = __float_as_uint(Bh[(kk + 4 + t4)*BS_STRIDE + col]);
                uint32_t bl0 = __float_as_uint(Bl[(kk + t4)*BS_STRIDE + col]);
                uint32_t bl1 = __float_as_uint(Bl[(kk + 4 + t4)*BS_STRIDE + col]);
                #pragma unroll
                for (int ma = 0; ma < 2; ma++){
                    mma8(acc[ma][jn], ah[ma][0], ah[ma][1], ah[ma][2], ah[ma][3], bh0, bh1);
                    mma8(acc[ma][jn], al[ma][0], al[ma][1], al[ma][2], al[ma][3], bh0, bh1);
                    mma8(acc[ma][jn], ah[ma][0], ah[ma][1], ah[ma][2], ah[ma][3], bl0, bl1);
                }
            }
        }
        __syncthreads();
    }

    #pragma unroll
    for (int ma = 0; ma < 2; ma++){
        #pragma unroll
        for (int jn = 0; jn < 8; jn++){
            size_t row0 = (size_t)bm + wm + ma*16 + g4;
            int     colb = bn + wn + jn*8 + t4*2;
            float2 bv = *(const float2*)&bias[colb];
            float2 lo = { acc[ma][jn][0] + bv.x, acc[ma][jn][1] + bv.y };
            float2 hi = { acc[ma][jn][2] + bv.x, acc[ma][jn][3] + bv.y };
            *(float2*)&C[row0*N + colb]     = lo;
            *(float2*)&C[(row0+8)*N + colb] = hi;
        }
    }
}

// ---------------- GraphNorm stats: per-chunk partials, no atomics ----------------
__global__ void k_stats(int n, int f){
    int g = blockIdx.x, fi = threadIdx.x;
    int p = blockIdx.y;
    int ch = (n + 15)/16;
    int s0 = p*ch, s1 = min(s0 + ch, n);
    float s = 0.f, s2 = 0.f;
    const float* base = g_AGG + (size_t)g*n*f + fi;
    for (int i = s0; i < s1; i++){
        float v = base[(size_t)i*f];
        s += v; s2 += v*v;
    }
    int slot = (p*NG + g)*256 + fi;
    g_SP1[slot] = s;
    g_SP2[slot] = s2;
}
__global__ void k_finstats(const float* __restrict__ ga, int n, int f){
    int i = blockIdx.x*blockDim.x + threadIdx.x;   // over NG*256
    if (i >= NG*256) return;
    int fi = i & 255;
    if (fi >= f) return;
    int g = i >> 8;
    float s = 0.f, s2 = 0.f;
    #pragma unroll
    for (int p = 0; p < 16; p++){
        int slot = (p*NG + g)*256 + fi;
        s += g_SP1[slot]; s2 += g_SP2[slot];
    }
    float inv_n = 1.f/(float)n;
    float mu = s*inv_n;
    float m2 = s2*inv_n;
    float a = ga[fi];
    float var = m2 - mu*mu*a*(2.f - a);
    g_MU[i] = mu;
    g_RS[i] = rsqrtf(fmaxf(var, 0.f) + EPSN);
}
__global__ void k_ipn(const float* __restrict__ pw, int f){
    __shared__ float sh[256];
    float v = (threadIdx.x < f) ? pw[threadIdx.x] : 0.f;
    sh[threadIdx.x] = v*v;
    __syncthreads();
    for (int st = 128; st > 0; st >>= 1){
        if (threadIdx.x < st) sh[threadIdx.x] += sh[threadIdx.x + st];
        __syncthreads();
    }
    if (threadIdx.x == 0) g_IPN = rsqrtf(sh[0]);
}

// ---------------- score: norm+relu on the fly, warp per node ----------------
__global__ void k_score(const float* __restrict__ gw, const float* __restrict__ gb,
                        const float* __restrict__ ga, const float* __restrict__ pw,
                        int ntot, int n, int f){
    int node = (blockIdx.x*blockDim.x + threadIdx.x) >> 5;
    int lane = threadIdx.x & 31;
    if (node >= ntot) return;
    int g = node / n;
    float dot = 0.f;
    for (int fc = lane*4; fc < f; fc += 128){
        float4 v  = *(const float4*)&g_AGG[(size_t)node*f + fc];
        float4 mu = *(const float4*)&g_MU[g*256 + fc];
        float4 rs = *(const float4*)&g_RS[g*256 + fc];
        float4 w  = *(const float4*)&gw[fc];
        float4 b  = *(const float4*)&gb[fc];
        float4 a  = *(const float4*)&ga[fc];
        float4 p  = *(const float4*)&pw[fc];
        float x0 = fmaxf(w.x*(v.x - a.x*mu.x)*rs.x + b.x, 0.f);
        float x1 = fmaxf(w.y*(v.y - a.y*mu.y)*rs.y + b.y, 0.f);
        float x2 = fmaxf(w.z*(v.z - a.z*mu.z)*rs.z + b.z, 0.f);
        float x3 = fmaxf(w.w*(v.w - a.w*mu.w)*rs.w + b.w, 0.f);
        dot += x0*p.x + x1*p.y + x2*p.z + x3*p.w;
    }
    #pragma unroll
    for (int o = 16; o > 0; o >>= 1) dot += __shfl_xor_sync(0xFFFFFFFF, dot, o);
    if (lane == 0) g_SCORE[node] = tanhf(dot*g_IPN);
}

// ---------------- per-graph exact top-k ----------------
__global__ void k_topk(int n, int k, int nxt){
    __shared__ unsigned keys[4096];
    __shared__ int hist[256];
    __shared__ unsigned sh_prefix;
    __shared__ int sh_rem;
    __shared__ int sg[512], se[512];
    __shared__ int base_g, base_e;

    int g = blockIdx.x;
    int tid = threadIdx.x;
    if (g == 0 && tid == 0) g_ECNT[nxt] = 0;
    const float* sc = g_SCORE + (size_t)g*n;

    for (int i = tid; i < n; i += blockDim.x){
        unsigned u = __float_as_uint(sc[i]);
        u = (u & 0x80000000u) ? ~u : (u | 0x80000000u);
        keys[i] = u;
    }
    if (tid == 0){ sh_prefix = 0u; sh_rem = k; }
    __syncthreads();

    for (int shift = 24; shift >= 0; shift -= 8){
        for (int i = tid; i < 256; i += blockDim.x) hist[i] = 0;
        __syncthreads();
        unsigned pmask = (shift == 24) ? 0u : (0xFFFFFFFFu << (shift + 8));
        unsigned pref = sh_prefix;
        for (int i = tid; i < n; i += blockDim.x){
            unsigned u = keys[i];
            if ((u & pmask) == pref) atomicAdd(&hist[(u >> shift) & 0xFF], 1);
        }
        __syncthreads();
        if (tid == 0){
            int rem = sh_rem, b;
            for (b = 255; b >= 0; b--){
                if (rem <= hist[b]) break;
                rem -= hist[b];
            }
            sh_prefix |= ((unsigned)b) << shift;
            sh_rem = rem;
        }
        __syncthreads();
    }
    unsigned thr = sh_prefix;
    int need = sh_rem;
    if (tid == 0){ base_g = 0; base_e = 0; }
    __syncthreads();

    for (int c0 = 0; c0 < n; c0 += blockDim.x){
        int i = c0 + tid;
        int gf = 0, ef = 0;
        if (i < n){
            unsigned u = keys[i];
            gf = (u > thr);
            ef = (u == thr);
        }
        sg[tid] = gf; se[tid] = ef;
        __syncthreads();
        for (int st = 1; st < blockDim.x; st <<= 1){
            int vg = 0, ve = 0;
            if (tid >= st){ vg = sg[tid-st]; ve = se[tid-st]; }
            __syncthreads();
            sg[tid] += vg; se[tid] += ve;
            __syncthreads();
        }
        if (i < n){
            int g_before = base_g + sg[tid] - gf;
            int e_before = base_e + se[tid] - ef;
            bool kept = gf || (ef && (e_before < need));
            int oldg = g*n + i;
            if (kept){
                int newlocal = g_before + min(e_before, need);
                int newglobal = g*k + newlocal;
                g_MAP[oldg]        = newglobal;
                g_PERMG[newglobal] = oldg;
                g_GATE[newglobal]  = sc[i];
            } else {
                g_MAP[oldg] = -1;
            }
        }
        __syncthreads();
        if (tid == 0){ base_g += sg[blockDim.x-1]; base_e += se[blockDim.x-1]; }
        __syncthreads();
    }
}

// ---------------- gather kept nodes with fused norm+relu+gate ----------------
__global__ void k_gather_norm(const float* __restrict__ gw, const float* __restrict__ gb,
                              const float* __restrict__ ga,
                              int tot_new, int n, int f){
    int per = f >> 2;
    size_t idx = (size_t)blockIdx.x*blockDim.x + threadIdx.x;
    if (idx >= (size_t)tot_new*per) return;
    int j  = (int)(idx / per);
    int fc = (int)(idx % per)*4;
    int old = g_PERMG[j];
    int g = old / n;
    float gv = g_GATE[j];
    float4 v  = *(const float4*)&g_AGG[(size_t)old*f + fc];
    float4 mu = *(const float4*)&g_MU[g*256 + fc];
    float4 rs = *(const float4*)&g_RS[g*256 + fc];
    float4 w  = *(const float4*)&gw[fc];
    float4 b  = *(const float4*)&gb[fc];
    float4 a  = *(const float4*)&ga[fc];
    float4 o;
    o.x = fmaxf(w.x*(v.x - a.x*mu.x)*rs.x + b.x, 0.f)*gv;
    o.y = fmaxf(w.y*(v.y - a.y*mu.y)*rs.y + b.y, 0.f)*gv;
    o.z = fmaxf(w.z*(v.z - a.z*mu.z)*rs.z + b.z, 0.f)*gv;
    o.w = fmaxf(w.w*(v.w - a.w*mu.w)*rs.w + b.w, 0.f)*gv;
    *(float4*)&g_X[(size_t)j*f + fc] = o;
}

// ---------------- remap + compact edges + count next in-degrees ----------------
__global__ void k_remap(int cur){
    int e = blockIdx.x*blockDim.x + threadIdx.x;
    if (e >= g_ECNT[cur]) return;
    int s = g_MAP[g_ESRC[cur][e]];
    int d = g_MAP[g_EDST[cur][e]];
    if (s >= 0 && d >= 0){
        int p = atomicAdd(&g_ECNT[cur^1], 1);
        g_ESRC[cur^1][p] = s;
        g_EDST[cur^1][p] = d;
        atomicAdd(&g_CNT[d], 1);
    }
}

// ---------------- readout ----------------
__global__ void k_readout(){
    int gg = blockIdx.x;
    int f  = threadIdx.x;
    const float* base = g_X + (size_t)gg*512*256;
    float s = 0.f, mx = -INFINITY;
    for (int i = 0; i < 512; i++){
        float v = base[(size_t)i*256 + f];
        s += v;
        mx = fmaxf(mx, v);
    }
    g_PMEAN[gg*256 + f] = s*(1.f/512.f);
    g_PMAX [gg*256 + f] = mx;
}

__global__ void k_final(float* __restrict__ out){
    int idx = blockIdx.x*blockDim.x + threadIdx.x;
    if (idx >= BATCH*512) return;
    int b = idx / 512, c = idx % 512;
    float acc = 0.f;
    if (c < 256){
        for (int t = 0; t < TS; t++) acc += g_PMEAN[(t*BATCH + b)*256 + c];
    } else {
        for (int t = 0; t < TS; t++) acc += g_PMAX[(t*BATCH + b)*256 + (c-256)];
    }
    out[idx] = acc*(1.f/(float)TS);
}

// ---------------- host orchestration ----------------
extern "C" void kernel_launch(void* const* d_in, const int* in_sizes, int n_in,
                              void* d_out, int out_size){
    const float* x_seq = (const float*)d_in[0];
    const int*   ei    = (const int*)  d_in[1];
    const float* W [3] = {(const float*)d_in[2],  (const float*)d_in[4],  (const float*)d_in[6]};
    const float* bb[3] = {(const float*)d_in[3],  (const float*)d_in[5],  (const float*)d_in[7]};
    const float* gw[3] = {(const float*)d_in[8],  (const float*)d_in[11], (const float*)d_in[14]};
    const float* gb[3] = {(const float*)d_in[9],  (const float*)d_in[12], (const float*)d_in[15]};
    const float* ga[3] = {(const float*)d_in[10], (const float*)d_in[13], (const float*)d_in[16]};
    const float* pw[3] = {(const float*)d_in[17], (const float*)d_in[18], (const float*)d_in[19]};
    float* out = (float*)d_out;

    float *pS, *pX, *pAGG;
    int *pCNT, *pCUR;
    cudaGetSymbolAddress((void**)&pS,   g_S);
    cudaGetSymbolAddress((void**)&pX,   g_X);
    cudaGetSymbolAddress((void**)&pAGG, g_AGG);
    cudaGetSymbolAddress((void**)&pCNT, g_CNT);
    cudaGetSymbolAddress((void**)&pCUR, g_CUR);

    cudaFuncSetAttribute(k_gemm_tc, cudaFuncAttributeMaxDynamicSharedMemorySize, SM_TOT);

    const int nin [3] = {4096, 2048, 1024};
    const int nk  [3] = {2048, 1024, 512};
    const int fin [3] = {100, 128, 128};
    const int fout[3] = {128, 128, 256};

    // layer-1 prep: zero counts, init edges with fused counting
    k_zero2i<<<(NG*NPG + 255)/256, 256>>>(pCNT, pCUR, NG*NPG);
    k_edge_init<<<NEDGE/256, 256>>>(ei);

    const float* A = x_seq;
    for (int l = 0; l < 3; l++){
        int n = nin[l], k = nk[l], fi = fin[l], fo = fout[l];
        int ntot = NG * n;
        int cur = l & 1, nxt = cur ^ 1;
        int nb = ntot / 512;
        int wpn = (fi + 127)/128;

        // CSR build (CNT already counted by edge_init / previous remap)
        k_scan1<<<nb, 512>>>(ntot);
        k_scan2<<<1, 1024>>>(nb);
        k_scan3d<<<nb, 512>>>(ntot);
        k_fill <<<NEDGE/256, 256>>>(cur);

        // GCN: aggregate-first, then GEMM with fused bias
        k_aggregate<<<ntot*wpn/8, 256>>>(A, ntot, fi, wpn);
        k_gemm_tc<<<dim3(fo/128, ntot/128), 256, SM_TOT>>>(pS, W[l], bb[l], pAGG, ntot, fo, fi);

        // GraphNorm stats + score
        k_stats<<<dim3(NG, 16), fo>>>(n, fo);
        k_finstats<<<(NG*256 + 255)/256, 256>>>(ga[l], n, fo);
        k_ipn<<<1, 256>>>(pw[l], fo);
        k_score<<<ntot/8, 256>>>(gw[l], gb[l], ga[l], pw[l], ntot, n, fo);

        // TopK pool
        k_topk<<<NG, 512>>>(n, k, nxt);
        int tot_new = NG * k;
        if (l < 2){
            k_zero2i<<<(tot_new + 255)/256, 256>>>(pCNT, pCUR, tot_new);
            k_remap<<<NEDGE/256, 256>>>(cur);
        }
        k_gather_norm<<<(int)(((size_t)tot_new*(fo/4) + 255)/256), 256>>>(gw[l], gb[l], ga[l], tot_new, n, fo);

        A = pX;
    }

    k_readout<<<NG, 256>>>();
    k_final<<<(BATCH*512 + 255)/256, 256>>>(out);
}

// round 6
// speedup vs baseline: 2.8325x; 1.4190x over previous
#include <cuda_runtime.h>
#include <math.h>
#include <stdint.h>

// ---------------- problem constants ----------------
#define TS     8
#define BATCH  16
#define NPG    4096
#define NEDGE  (TS*BATCH*32768)   // 4,194,304 edges (all timesteps, layer 1)
#define NG     (TS*BATCH)         // 128 graphs
#define EPSN   1e-5f
#define MAXN   524288

// ---------------- static device scratch ----------------
__device__ float g_S  [67108864];   // aggregated input  S = A_norm * X
__device__ float g_AGG[67108864];   // gcn output Y = S*W + b
__device__ float g_X  [33554432];   // compacted layer input (normalized+gated)
__device__ float g_DINV[MAXN];
__device__ float g_SCORE[MAXN];
__device__ int   g_MAP [MAXN];
__device__ int   g_PERMG[262144];
__device__ float g_GATE [262144];
__device__ int   g_CNT[MAXN];
__device__ int   g_CUR[MAXN];
__device__ int   g_ROW[MAXN];
__device__ int   g_BSUM[1024];
__device__ int   g_CSRC[NEDGE];
__device__ float g_CW [NEDGE];
__device__ int   g_ESRC[2][NEDGE];
__device__ int   g_EDST[2][NEDGE];
__device__ int   g_ECNT[2];
__device__ float g_SP1[NG*256];     // stats accum (sum)   — self-zeroed by finstats
__device__ float g_SP2[NG*256];     // stats accum (sumsq)
__device__ float g_MU [NG*256];
__device__ float g_RS [NG*256];
__device__ float g_IPN;
__device__ float g_PMEAN[NG*256];
__device__ float g_PMAX [NG*256];

// ---------------- utility ----------------
__global__ void k_zero2i(int* a, int* b, int cnt){
    int i = blockIdx.x*blockDim.x + threadIdx.x;
    if (i < cnt){ a[i] = 0; b[i] = 0; }
}
__global__ void k_zeroSP(){
    int i = blockIdx.x*blockDim.x + threadIdx.x;
    if (i < NG*256){ g_SP1[i] = 0.f; g_SP2[i] = 0.f; }
}

__global__ void k_edge_init(const int* __restrict__ ei){
    int idx = blockIdx.x*blockDim.x + threadIdx.x;
    if (idx == 0){ g_ECNT[0] = NEDGE; g_ECNT[1] = 0; }
    if (idx >= NEDGE) return;
    const int E = 32768*BATCH;
    int t = idx / E, e = idx % E;
    int base = t * (BATCH*NPG);
    int s = ei[(size_t)t*2*E + e]     + base;
    int d = ei[(size_t)t*2*E + E + e] + base;
    g_ESRC[0][idx] = s;
    g_EDST[0][idx] = d;
    atomicAdd(&g_CNT[d], 1);
}

// ---------------- CSR build ----------------
__global__ void k_scan1(int n){
    __shared__ int sh[512];
    int i = blockIdx.x*512 + threadIdx.x;
    int v = (i < n) ? g_CNT[i] : 0;
    sh[threadIdx.x] = v;
    __syncthreads();
    for (int st = 1; st < 512; st <<= 1){
        int t = (threadIdx.x >= st) ? sh[threadIdx.x - st] : 0;
        __syncthreads();
        sh[threadIdx.x] += t;
        __syncthreads();
    }
    if (i < n) g_ROW[i] = sh[threadIdx.x] - v;
    if (threadIdx.x == 511) g_BSUM[blockIdx.x] = sh[511];
}
// scan finish (block-prefix computed locally) + dinv, scan2 eliminated
__global__ void k_scan3d(int n){
    __shared__ int sh[512];
    int bid = blockIdx.x, tid = threadIdx.x;
    int acc = 0;
    for (int j = tid; j < bid; j += 512) acc += g_BSUM[j];
    sh[tid] = acc;
    __syncthreads();
    for (int st = 256; st > 0; st >>= 1){
        if (tid < st) sh[tid] += sh[tid + st];
        __syncthreads();
    }
    int base = sh[0];
    int i = bid*512 + tid;
    if (i < n){
        g_ROW[i] += base;
        g_DINV[i] = rsqrtf(1.f + (float)g_CNT[i]);
    }
}

__global__ void k_fill(int cur){
    int e = blockIdx.x*blockDim.x + threadIdx.x;
    if (e >= g_ECNT[cur]) return;
    int s = g_ESRC[cur][e], d = g_EDST[cur][e];
    int slot = g_ROW[d] + atomicAdd(&g_CUR[d], 1);
    g_CSRC[slot] = s;
    g_CW[slot]   = g_DINV[s]*g_DINV[d];
}

// ---------------- aggregate-first: S[d] = sum w_e X[s] + dinv[d]^2 X[d] ----------
__global__ void k_aggregate(const float* __restrict__ X, int ntot, int f, int wpn){
    int gw = (blockIdx.x*blockDim.x + threadIdx.x) >> 5;
    int lane = threadIdx.x & 31;
    int node = gw / wpn;
    if (node >= ntot) return;
    int fb = (gw % wpn)*128 + lane*4;
    if (fb >= f) return;
    int r0 = g_ROW[node];
    int cnt = g_CNT[node];
    float ax = 0.f, ay = 0.f, az = 0.f, aw = 0.f;
    for (int e = r0; e < r0 + cnt; e++){
        int s = g_CSRC[e];
        float w = g_CW[e];
        float4 v = *(const float4*)&X[(size_t)s*f + fb];
        ax += w*v.x; ay += w*v.y; az += w*v.z; aw += w*v.w;
    }
    float di = g_DINV[node];
    float c = di*di;
    float4 sv = *(const float4*)&X[(size_t)node*f + fb];
    float4 o = { ax + c*sv.x, ay + c*sv.y, az + c*sv.z, aw + c*sv.w };
    *(float4*)&g_S[(size_t)node*f + fb] = o;
}

// ---------------- tf32-split GEMM + fused bias + fused GraphNorm partial stats ---
#define AS_STRIDE 36
#define BS_STRIDE 136
#define SM_AH 0
#define SM_AL (128*AS_STRIDE)
#define SM_BH (2*128*AS_STRIDE)
#define SM_BL (2*128*AS_STRIDE + 32*BS_STRIDE)
#define SM_TOT ((2*128*AS_STRIDE + 2*32*BS_STRIDE)*4)

__device__ __forceinline__ float f2hi(float v){
    float h;
    asm("cvt.rna.tf32.f32 %0, %1;" : "=f"(h) : "f"(v));
    return h;
}
__device__ __forceinline__ void mma8(float* d, uint32_t a0, uint32_t a1, uint32_t a2, uint32_t a3,
                                     uint32_t b0, uint32_t b1){
    asm volatile("mma.sync.aligned.m16n8k8.row.col.f32.tf32.tf32.f32 "
        "{%0,%1,%2,%3}, {%4,%5,%6,%7}, {%8,%9}, {%0,%1,%2,%3};"
        : "+f"(d[0]), "+f"(d[1]), "+f"(d[2]), "+f"(d[3])
        : "r"(a0), "r"(a1), "r"(a2), "r"(a3), "r"(b0), "r"(b1));
}

__global__ void __launch_bounds__(256) k_gemm_tc(const float* __restrict__ A,
                                                 const float* __restrict__ W,
                                                 const float* __restrict__ bias,
                                                 float* __restrict__ C,
                                                 int M, int N, int K, int npg){
    extern __shared__ float sm[];
    float* Ah = sm + SM_AH;
    float* Al = sm + SM_AL;
    float* Bh = sm + SM_BH;
    float* Bl = sm + SM_BL;
    const int tid = threadIdx.x, lane = tid & 31, wid = tid >> 5;
    const int wm = (wid >> 1)*32, wn = (wid & 1)*64;
    const int bm = blockIdx.y*128, bn = blockIdx.x*128;
    const int g4 = lane >> 2, t4 = lane & 3;

    float acc[2][8][4] = {};

    const int K8 = ((K + 7)/8)*8;            // pad only to k8 atom
    const int nch = (K8 + 31)/32;
    for (int kc = 0; kc < nch; kc++){
        const int k0 = kc*32;
        const int kend = min(32, K8 - k0);
        #pragma unroll
        for (int it = 0; it < 16; it++){
            int idx = it*256 + tid;
            int col = idx & 31, row = idx >> 5;
            int kg = k0 + col;
            float v = (kg < K) ? A[(size_t)(bm+row)*K + kg] : 0.f;
            float h = f2hi(v);
            Ah[row*AS_STRIDE + col] = h;
            Al[row*AS_STRIDE + col] = v - h;
        }
        #pragma unroll
        for (int it = 0; it < 16; it++){
            int idx = it*256 + tid;
            int nc = idx & 127, kr = idx >> 7;
            int kg = k0 + kr;
            float v = (kg < K) ? W[(size_t)kg*N + bn + nc] : 0.f;
            float h = f2hi(v);
            Bh[kr*BS_STRIDE + nc] = h;
            Bl[kr*BS_STRIDE + nc] = v - h;
        }
        __syncthreads();

        for (int kk = 0; kk < kend; kk += 8){
            uint32_t ah[2][4], al[2][4];
            #pragma unroll
            for (int ma = 0; ma < 2; ma++){
                int r0 = (wm + ma*16 + g4)*AS_STRIDE;
                int c0 = kk + t4;
                ah[ma][0] = __float_as_uint(Ah[r0 + c0]);
                ah[ma][1] = __float_as_uint(Ah[r0 + 8*AS_STRIDE + c0]);
                ah[ma][2] = __float_as_uint(Ah[r0 + c0 + 4]);
                ah[ma][3] = __float_as_uint(Ah[r0 + 8*AS_STRIDE + c0 + 4]);
                al[ma][0] = __float_as_uint(Al[r0 + c0]);
                al[ma][1] = __float_as_uint(Al[r0 + 8*AS_STRIDE + c0]);
                al[ma][2] = __float_as_uint(Al[r0 + c0 + 4]);
                al[ma][3] = __float_as_uint(Al[r0 + 8*AS_STRIDE + c0 + 4]);
            }
            #pragma unroll
            for (int jn = 0; jn < 8; jn++){
                int col = wn + jn*8 + g4;
                uint32_t bh0 = __float_as_uint(Bh[(kk + t4)*BS_STRIDE + col]);
                uint32_t bh1 = __float_as_uint(Bh[(kk + 4 + t4)*BS_STRIDE + col]);
                uint32_t bl0 = __float_as_uint(Bl[(kk + t4)*BS_STRIDE + col]);
                uint32_t bl1 = __float_as_uint(Bl[(kk + 4 + t4)*BS_STRIDE + col]);
                #pragma unroll
                for (int ma = 0; ma < 2; ma++){
                    mma8(acc[ma][jn], ah[ma][0], ah[ma][1], ah[ma][2], ah[ma][3], bh0, bh1);
                    mma8(acc[ma][jn], al[ma][0], al[ma][1], al[ma][2], al[ma][3], bh0, bh1);
                    mma8(acc[ma][jn], ah[ma][0], ah[ma][1], ah[ma][2], ah[ma][3], bl0, bl1);
                }
            }
        }
        __syncthreads();
    }

    // epilogue: bias, store, per-column partial stats
    float ps[16], ps2[16];
    #pragma unroll
    for (int i = 0; i < 16; i++){ ps[i] = 0.f; ps2[i] = 0.f; }

    #pragma unroll
    for (int ma = 0; ma < 2; ma++){
        #pragma unroll
        for (int jn = 0; jn < 8; jn++){
            size_t row0 = (size_t)bm + wm + ma*16 + g4;
            int    colb = bn + wn + jn*8 + t4*2;
            float2 bv = *(const float2*)&bias[colb];
            float a0 = acc[ma][jn][0] + bv.x, a1 = acc[ma][jn][1] + bv.y;
            float a2 = acc[ma][jn][2] + bv.x, a3 = acc[ma][jn][3] + bv.y;
            float2 lo = { a0, a1 };
            float2 hi = { a2, a3 };
            *(float2*)&C[row0*N + colb]     = lo;
            *(float2*)&C[(row0+8)*N + colb] = hi;
            ps [jn*2+0] += a0 + a2;
            ps [jn*2+1] += a1 + a3;
            ps2[jn*2+0] += a0*a0 + a2*a2;
            ps2[jn*2+1] += a1*a1 + a3*a3;
        }
    }
    #pragma unroll
    for (int o = 4; o < 32; o <<= 1){
        #pragma unroll
        for (int i = 0; i < 16; i++){
            ps [i] += __shfl_xor_sync(0xFFFFFFFF, ps [i], o);
            ps2[i] += __shfl_xor_sync(0xFFFFFFFF, ps2[i], o);
        }
    }
    if (lane < 4){
        int g = bm / npg;
        #pragma unroll
        for (int i = 0; i < 16; i++){
            int colg = bn + wn + (i >> 1)*8 + t4*2 + (i & 1);
            atomicAdd(&g_SP1[g*256 + colg], ps[i]);
            atomicAdd(&g_SP2[g*256 + colg], ps2[i]);
        }
    }
}

// ---------------- finalize stats (+ pw norm), self-zero partials ----------------
__global__ void k_finstats(const float* __restrict__ ga, const float* __restrict__ pw,
                           int n, int f){
    int i = blockIdx.x*blockDim.x + threadIdx.x;
    if (i < NG*256){
        int fi = i & 255;
        if (fi < f){
            float s = g_SP1[i], s2 = g_SP2[i];
            g_SP1[i] = 0.f; g_SP2[i] = 0.f;
            float inv_n = 1.f/(float)n;
            float mu = s*inv_n;
            float m2 = s2*inv_n;
            float a = ga[fi];
            float var = m2 - mu*mu*a*(2.f - a);
            g_MU[i] = mu;
            g_RS[i] = rsqrtf(fmaxf(var, 0.f) + EPSN);
        }
    }
    if (blockIdx.x == 0){
        __shared__ float sh[256];
        float v = (threadIdx.x < f) ? pw[threadIdx.x] : 0.f;
        sh[threadIdx.x] = v*v;
        __syncthreads();
        for (int st = 128; st > 0; st >>= 1){
            if (threadIdx.x < st) sh[threadIdx.x] += sh[threadIdx.x + st];
            __syncthreads();
        }
        if (threadIdx.x == 0) g_IPN = rsqrtf(sh[0]);
    }
}

// ---------------- score: norm+relu on the fly, warp per node ----------------
__global__ void k_score(const float* __restrict__ gw, const float* __restrict__ gb,
                        const float* __restrict__ ga, const float* __restrict__ pw,
                        int ntot, int n, int f){
    int node = (blockIdx.x*blockDim.x + threadIdx.x) >> 5;
    int lane = threadIdx.x & 31;
    if (node >= ntot) return;
    int g = node / n;
    float dot = 0.f;
    for (int fc = lane*4; fc < f; fc += 128){
        float4 v  = *(const float4*)&g_AGG[(size_t)node*f + fc];
        float4 mu = *(const float4*)&g_MU[g*256 + fc];
        float4 rs = *(const float4*)&g_RS[g*256 + fc];
        float4 w  = *(const float4*)&gw[fc];
        float4 b  = *(const float4*)&gb[fc];
        float4 a  = *(const float4*)&ga[fc];
        float4 p  = *(const float4*)&pw[fc];
        float x0 = fmaxf(w.x*(v.x - a.x*mu.x)*rs.x + b.x, 0.f);
        float x1 = fmaxf(w.y*(v.y - a.y*mu.y)*rs.y + b.y, 0.f);
        float x2 = fmaxf(w.z*(v.z - a.z*mu.z)*rs.z + b.z, 0.f);
        float x3 = fmaxf(w.w*(v.w - a.w*mu.w)*rs.w + b.w, 0.f);
        dot += x0*p.x + x1*p.y + x2*p.z + x3*p.w;
    }
    #pragma unroll
    for (int o = 16; o > 0; o >>= 1) dot += __shfl_xor_sync(0xFFFFFFFF, dot, o);
    if (lane == 0) g_SCORE[node] = tanhf(dot*g_IPN);
}

// ---------------- per-graph exact top-k ----------------
__global__ void k_topk(int n, int k, int nxt){
    __shared__ unsigned keys[4096];
    __shared__ int hist[256];
    __shared__ unsigned sh_prefix;
    __shared__ int sh_rem;
    __shared__ int sg[512], se[512];
    __shared__ int base_g, base_e;

    int g = blockIdx.x;
    int tid = threadIdx.x;
    if (g == 0 && tid == 0) g_ECNT[nxt] = 0;
    const float* sc = g_SCORE + (size_t)g*n;

    for (int i = tid; i < n; i += blockDim.x){
        unsigned u = __float_as_uint(sc[i]);
        u = (u & 0x80000000u) ? ~u : (u | 0x80000000u);
        keys[i] = u;
    }
    if (tid == 0){ sh_prefix = 0u; sh_rem = k; }
    __syncthreads();

    for (int shift = 24; shift >= 0; shift -= 8){
        for (int i = tid; i < 256; i += blockDim.x) hist[i] = 0;
        __syncthreads();
        unsigned pmask = (shift == 24) ? 0u : (0xFFFFFFFFu << (shift + 8));
        unsigned pref = sh_prefix;
        for (int i = tid; i < n; i += blockDim.x){
            unsigned u = keys[i];
            if ((u & pmask) == pref) atomicAdd(&hist[(u >> shift) & 0xFF], 1);
        }
        __syncthreads();
        if (tid == 0){
            int rem = sh_rem, b;
            for (b = 255; b >= 0; b--){
                if (rem <= hist[b]) break;
                rem -= hist[b];
            }
            sh_prefix |= ((unsigned)b) << shift;
            sh_rem = rem;
        }
        __syncthreads();
    }
    unsigned thr = sh_prefix;
    int need = sh_rem;
    if (tid == 0){ base_g = 0; base_e = 0; }
    __syncthreads();

    for (int c0 = 0; c0 < n; c0 += blockDim.x){
        int i = c0 + tid;
        int gf = 0, ef = 0;
        if (i < n){
            unsigned u = keys[i];
            gf = (u > thr);
            ef = (u == thr);
        }
        sg[tid] = gf; se[tid] = ef;
        __syncthreads();
        for (int st = 1; st < blockDim.x; st <<= 1){
            int vg = 0, ve = 0;
            if (tid >= st){ vg = sg[tid-st]; ve = se[tid-st]; }
            __syncthreads();
            sg[tid] += vg; se[tid] += ve;
            __syncthreads();
        }
        if (i < n){
            int g_before = base_g + sg[tid] - gf;
            int e_before = base_e + se[tid] - ef;
            bool kept = gf || (ef && (e_before < need));
            int oldg = g*n + i;
            if (kept){
                int newlocal = g_before + min(e_before, need);
                int newglobal = g*k + newlocal;
                g_MAP[oldg]        = newglobal;
                g_PERMG[newglobal] = oldg;
                g_GATE[newglobal]  = sc[i];
            } else {
                g_MAP[oldg] = -1;
            }
        }
        __syncthreads();
        if (tid == 0){ base_g += sg[blockDim.x-1]; base_e += se[blockDim.x-1]; }
        __syncthreads();
    }
}

// ---------------- gather kept nodes with fused norm+relu+gate (layers 1,2) ------
__global__ void k_gather_norm(const float* __restrict__ gw, const float* __restrict__ gb,
                              const float* __restrict__ ga,
                              int tot_new, int n, int f){
    int per = f >> 2;
    size_t idx = (size_t)blockIdx.x*blockDim.x + threadIdx.x;
    if (idx >= (size_t)tot_new*per) return;
    int j  = (int)(idx / per);
    int fc = (int)(idx % per)*4;
    int old = g_PERMG[j];
    int g = old / n;
    float gv = g_GATE[j];
    float4 v  = *(const float4*)&g_AGG[(size_t)old*f + fc];
    float4 mu = *(const float4*)&g_MU[g*256 + fc];
    float4 rs = *(const float4*)&g_RS[g*256 + fc];
    float4 w  = *(const float4*)&gw[fc];
    float4 b  = *(const float4*)&gb[fc];
    float4 a  = *(const float4*)&ga[fc];
    float4 o;
    o.x = fmaxf(w.x*(v.x - a.x*mu.x)*rs.x + b.x, 0.f)*gv;
    o.y = fmaxf(w.y*(v.y - a.y*mu.y)*rs.y + b.y, 0.f)*gv;
    o.z = fmaxf(w.z*(v.z - a.z*mu.z)*rs.z + b.z, 0.f)*gv;
    o.w = fmaxf(w.w*(v.w - a.w*mu.w)*rs.w + b.w, 0.f)*gv;
    *(float4*)&g_X[(size_t)j*f + fc] = o;
}

// ---------------- remap + compact edges + count next in-degrees ----------------
__global__ void k_remap(int cur){
    int e = blockIdx.x*blockDim.x + threadIdx.x;
    if (e >= g_ECNT[cur]) return;
    int s = g_MAP[g_ESRC[cur][e]];
    int d = g_MAP[g_EDST[cur][e]];
    if (s >= 0 && d >= 0){
        int p = atomicAdd(&g_ECNT[cur^1], 1);
        g_ESRC[cur^1][p] = s;
        g_EDST[cur^1][p] = d;
        atomicAdd(&g_CNT[d], 1);
    }
}

// ---------------- fused L3 gather + readout: norm+gate on the fly ----------------
__global__ void k_readout(const float* __restrict__ gw, const float* __restrict__ gb,
                          const float* __restrict__ ga, int n){
    int gg = blockIdx.x;
    int f  = threadIdx.x;   // 256
    float w = gw[f], b = gb[f], a = ga[f];
    float mu = g_MU[gg*256 + f], rs = g_RS[gg*256 + f];
    float s = 0.f, mx = -INFINITY;
    for (int i = 0; i < 512; i++){
        int j = gg*512 + i;
        int old = g_PERMG[j];
        float gv = g_GATE[j];
        float v = g_AGG[(size_t)old*256 + f];
        float x = fmaxf(w*(v - a*mu)*rs + b, 0.f)*gv;
        s += x;
        mx = fmaxf(mx, x);
    }
    g_PMEAN[gg*256 + f] = s*(1.f/512.f);
    g_PMAX [gg*256 + f] = mx;
}

__global__ void k_final(float* __restrict__ out){
    int idx = blockIdx.x*blockDim.x + threadIdx.x;
    if (idx >= BATCH*512) return;
    int b = idx / 512, c = idx % 512;
    float acc = 0.f;
    if (c < 256){
        for (int t = 0; t < TS; t++) acc += g_PMEAN[(t*BATCH + b)*256 + c];
    } else {
        for (int t = 0; t < TS; t++) acc += g_PMAX[(t*BATCH + b)*256 + (c-256)];
    }
    out[idx] = acc*(1.f/(float)TS);
}

// ---------------- host orchestration ----------------
extern "C" void kernel_launch(void* const* d_in, const int* in_sizes, int n_in,
                              void* d_out, int out_size){
    const float* x_seq = (const float*)d_in[0];
    const int*   ei    = (const int*)  d_in[1];
    const float* W [3] = {(const float*)d_in[2],  (const float*)d_in[4],  (const float*)d_in[6]};
    const float* bb[3] = {(const float*)d_in[3],  (const float*)d_in[5],  (const float*)d_in[7]};
    const float* gw[3] = {(const float*)d_in[8],  (const float*)d_in[11], (const float*)d_in[14]};
    const float* gb[3] = {(const float*)d_in[9],  (const float*)d_in[12], (const float*)d_in[15]};
    const float* ga[3] = {(const float*)d_in[10], (const float*)d_in[13], (const float*)d_in[16]};
    const float* pw[3] = {(const float*)d_in[17], (const float*)d_in[18], (const float*)d_in[19]};
    float* out = (float*)d_out;

    float *pS, *pX, *pAGG;
    int *pCNT, *pCUR;
    cudaGetSymbolAddress((void**)&pS,   g_S);
    cudaGetSymbolAddress((void**)&pX,   g_X);
    cudaGetSymbolAddress((void**)&pAGG, g_AGG);
    cudaGetSymbolAddress((void**)&pCNT, g_CNT);
    cudaGetSymbolAddress((void**)&pCUR, g_CUR);

    cudaFuncSetAttribute(k_gemm_tc, cudaFuncAttributeMaxDynamicSharedMemorySize, SM_TOT);

    const int nin [3] = {4096, 2048, 1024};
    const int nk  [3] = {2048, 1024, 512};
    const int fin [3] = {100, 128, 128};
    const int fout[3] = {128, 128, 256};

    k_zero2i<<<(NG*NPG + 255)/256, 256>>>(pCNT, pCUR, NG*NPG);
    k_zeroSP<<<(NG*256 + 255)/256, 256>>>();
    k_edge_init<<<NEDGE/256, 256>>>(ei);

    const float* A = x_seq;
    for (int l = 0; l < 3; l++){
        int n = nin[l], k = nk[l], fi = fin[l], fo = fout[l];
        int ntot = NG * n;
        int cur = l & 1, nxt = cur ^ 1;
        int nb = ntot / 512;
        int wpn = (fi + 127)/128;

        // CSR build
        k_scan1<<<nb, 512>>>(ntot);
        k_scan3d<<<nb, 512>>>(ntot);
        k_fill <<<NEDGE/256, 256>>>(cur);

        // GCN: aggregate-first, GEMM with fused bias + stats partials
        k_aggregate<<<ntot*wpn/8, 256>>>(A, ntot, fi, wpn);
        k_gemm_tc<<<dim3(fo/128, ntot/128), 256, SM_TOT>>>(pS, W[l], bb[l], pAGG, ntot, fo, fi, n);

        // stats finalize (+ipn) and score
        k_finstats<<<(NG*256 + 255)/256, 256>>>(ga[l], pw[l], n, fo);
        k_score<<<ntot/8, 256>>>(gw[l], gb[l], ga[l], pw[l], ntot, n, fo);

        // TopK pool
        k_topk<<<NG, 512>>>(n, k, nxt);
        int tot_new = NG * k;
        if (l < 2){
            k_zero2i<<<(tot_new + 255)/256, 256>>>(pCNT, pCUR, tot_new);
            k_remap<<<NEDGE/256, 256>>>(cur);
            k_gather_norm<<<(int)(((size_t)tot_new*(fo/4) + 255)/256), 256>>>(gw[l], gb[l], ga[l], tot_new, n, fo);
            A = pX;
        }
    }

    // fused L3 gather + readout
    k_readout<<<NG, 256>>>(gw[2], gb[2], ga[2], nin[2]);
    k_final<<<(BATCH*512 + 255)/256, 256>>>(out);
}